// round 1
// baseline (speedup 1.0000x reference)
#include <cuda_runtime.h>
#include <math.h>

#define NB 4
#define SS 64
#define DM 512
#define NH 8
#define DHD 64
#define FF 2048
#define NL 2
#define NV 32128
#define NT 16

// ------------------------- device scratch (static: no allocs) -------------
static __device__ float g_x[NB*SS*DM];
static __device__ float g_h[NB*SS*DM];
static __device__ float g_q[NB*SS*DM];
static __device__ float g_k[NB*SS*DM];
static __device__ float g_v[NB*SS*DM];
static __device__ float g_att[NB*SS*DM];
static __device__ float g_f[NB*SS*FF];
static __device__ float g_hs[NB*SS*DM];
static __device__ float g_ck[NL*NB*SS*DM];     // cross K cache [L][B][S][D]
static __device__ float g_cv[NL*NB*SS*DM];
static __device__ float g_sk[NL*(NT+1)*NB*DM]; // self K cache [L][T][B][D]
static __device__ float g_sv[NL*(NT+1)*NB*DM];
static __device__ float g_ye[(NT+1)*NB*DM];    // soft-embedding history [T][B][D]
static __device__ float g_xd[NB*DM];
static __device__ float g_qd[NB*DM];
static __device__ float g_ad[NB*DM];
static __device__ float g_fd[NB*FF];
static __device__ float g_logits[NB*NV];
static __device__ float g_part[64*NB*DM];      // split-K partials for probs@emb

// ------------------------- kernels ---------------------------------------

__global__ void embed_kernel(const int* __restrict__ ids,
                             const float* __restrict__ emb,
                             float* __restrict__ x) {
    int r = blockIdx.x;
    int id = ids[r];
    const float4* src = (const float4*)(emb + (size_t)id * DM);
    float4* dst = (float4*)(x + (size_t)r * DM);
    for (int i = threadIdx.x; i < DM/4; i += blockDim.x) dst[i] = src[i];
}

__global__ void init_y0_kernel(const float* __restrict__ emb, float* __restrict__ ye) {
    int b = blockIdx.x;
    for (int i = threadIdx.x; i < DM; i += blockDim.x)
        ye[b*DM + i] = emb[i];   // PAD_ID = 0 -> emb row 0
}

__global__ void copyrow_kernel(const float* __restrict__ src, float* __restrict__ dst) {
    int i = blockIdx.x * blockDim.x + threadIdx.x;
    if (i < NB*DM) dst[i] = src[i];
}

// rows of 512, block per row
__global__ void rmsnorm_kernel(const float* __restrict__ x,
                               const float* __restrict__ ln,
                               float* __restrict__ out) {
    int r = blockIdx.x;
    __shared__ float red[256];
    float s = 0.f;
    for (int i = threadIdx.x; i < DM; i += 256) { float v = x[(size_t)r*DM + i]; s += v*v; }
    red[threadIdx.x] = s; __syncthreads();
    for (int st = 128; st > 0; st >>= 1) {
        if (threadIdx.x < st) red[threadIdx.x] += red[threadIdx.x + st];
        __syncthreads();
    }
    float scale = rsqrtf(red[0] / (float)DM + 1e-6f);
    for (int i = threadIdx.x; i < DM; i += 256)
        out[(size_t)r*DM + i] = x[(size_t)r*DM + i] * scale * ln[i];
}

// C[M,N] = op(A[M,K] @ W[K,N]); flags: 1=relu, 2=accumulate into C
// block: 128 threads = 128 cols, 16 rows; K tiled by 64.
__global__ void __launch_bounds__(128) gemm_kernel(
    const float* __restrict__ A, const float* __restrict__ W, float* __restrict__ C,
    int M, int N, int K, int flags) {
    __shared__ float xs[16][64];
    int n = blockIdx.x * 128 + threadIdx.x;
    int m0 = blockIdx.y * 16;
    float acc[16];
    #pragma unroll
    for (int i = 0; i < 16; i++) acc[i] = 0.f;
    for (int k0 = 0; k0 < K; k0 += 64) {
        for (int e = threadIdx.x; e < 16*64; e += 128) {
            int mi = e >> 6, kk = e & 63;
            xs[mi][kk] = A[(size_t)(m0 + mi) * K + k0 + kk];
        }
        __syncthreads();
        #pragma unroll 16
        for (int kk = 0; kk < 64; kk++) {
            float w = W[(size_t)(k0 + kk) * N + n];
            #pragma unroll
            for (int mi = 0; mi < 16; mi++) acc[mi] = fmaf(xs[mi][kk], w, acc[mi]);
        }
        __syncthreads();
    }
    #pragma unroll
    for (int mi = 0; mi < 16; mi++) {
        float r = acc[mi];
        if (flags & 1) r = fmaxf(r, 0.f);
        size_t o = (size_t)(m0 + mi) * N + n;
        if (flags & 2) C[o] += r; else C[o] = r;
    }
}

// decoder GEMV: 4 rows, optional fused RMSNorm (ln != null), flags: 1=relu 2=acc
// dynamic smem: 4*K floats. 128 threads = 128 cols per block.
__global__ void __launch_bounds__(128) gemv_kernel(
    const float* __restrict__ x, const float* __restrict__ W, float* __restrict__ out,
    int N, int K, const float* __restrict__ ln, int flags) {
    extern __shared__ float xs[];
    int tid = threadIdx.x;
    for (int e = tid; e < 4*K; e += 128) xs[e] = x[e];
    __syncthreads();
    if (ln) {
        __shared__ float red[4][128];
        float s0=0,s1=0,s2=0,s3=0;
        for (int k = tid; k < K; k += 128) {
            s0 += xs[k]*xs[k]; s1 += xs[K+k]*xs[K+k];
            s2 += xs[2*K+k]*xs[2*K+k]; s3 += xs[3*K+k]*xs[3*K+k];
        }
        red[0][tid]=s0; red[1][tid]=s1; red[2][tid]=s2; red[3][tid]=s3;
        __syncthreads();
        for (int st = 64; st > 0; st >>= 1) {
            if (tid < st)
                #pragma unroll
                for (int m = 0; m < 4; m++) red[m][tid] += red[m][tid+st];
            __syncthreads();
        }
        float sc[4];
        #pragma unroll
        for (int m = 0; m < 4; m++) sc[m] = rsqrtf(red[m][0] / (float)K + 1e-6f);
        for (int k = tid; k < K; k += 128) {
            float lw = ln[k];
            #pragma unroll
            for (int m = 0; m < 4; m++) xs[m*K+k] *= sc[m]*lw;
        }
        __syncthreads();
    }
    int n = blockIdx.x * 128 + tid;
    const float* x0 = xs; const float* x1 = xs+K; const float* x2 = xs+2*K; const float* x3 = xs+3*K;
    float a0=0,a1=0,a2=0,a3=0;
    #pragma unroll 16
    for (int k = 0; k < K; k++) {
        float w = W[(size_t)k * N + n];
        a0 = fmaf(x0[k], w, a0); a1 = fmaf(x1[k], w, a1);
        a2 = fmaf(x2[k], w, a2); a3 = fmaf(x3[k], w, a3);
    }
    float r[4] = {a0,a1,a2,a3};
    #pragma unroll
    for (int m = 0; m < 4; m++) {
        float v = r[m];
        if (flags & 1) v = fmaxf(v, 0.f);
        size_t o = (size_t)m * N + n;
        if (flags & 2) out[o] += v; else out[o] = v;
    }
}

// attention: one block per (query-row, head). 64 threads. Tk <= 64.
// K/V addressing: base + b*kbs + j*kts + h*64 + d
__global__ void __launch_bounds__(64) attn_kernel(
    const float* __restrict__ q, const float* __restrict__ kc, const float* __restrict__ vc,
    float* __restrict__ out, int Tq, int Tk, long long kbs, long long kts,
    const float* __restrict__ mask) {
    int h  = blockIdx.x & (NH-1);
    int rq = blockIdx.x >> 3;
    int b  = rq / Tq;
    __shared__ float qv[64], s[64], red[64];
    int tid = threadIdx.x;
    qv[tid] = q[(size_t)rq*DM + h*DHD + tid];
    __syncthreads();
    float sc;
    if (tid < Tk) {
        const float* kp = kc + (size_t)b*kbs + (size_t)tid*kts + h*DHD;
        float dot = 0.f;
        #pragma unroll
        for (int d = 0; d < DHD; d++) dot = fmaf(qv[d], kp[d], dot);
        sc = dot * 0.125f;
        if (mask) sc += (1.f - mask[b*Tk + tid]) * (-1e9f);
    } else sc = -3.0e38f;
    s[tid] = sc; red[tid] = sc;
    __syncthreads();
    for (int st = 32; st > 0; st >>= 1) {
        if (tid < st) red[tid] = fmaxf(red[tid], red[tid+st]);
        __syncthreads();
    }
    float mx = red[0];
    __syncthreads();
    float e = (tid < Tk) ? expf(s[tid] - mx) : 0.f;
    s[tid] = e; red[tid] = e;
    __syncthreads();
    for (int st = 32; st > 0; st >>= 1) {
        if (tid < st) red[tid] += red[tid+st];
        __syncthreads();
    }
    float inv = 1.f / red[0];
    float o = 0.f;
    const float* vb = vc + (size_t)b*kbs + h*DHD;
    for (int j = 0; j < Tk; j++) o = fmaf(s[j], vb[(size_t)j*kts + tid], o);
    out[(size_t)rq*DM + h*DHD + tid] = o * inv;
}

// softmax + argmax over V per batch row; writes probs into d_out, pred flag tail
__global__ void __launch_bounds__(1024) softmax_kernel(
    const float* __restrict__ lg_all, float* __restrict__ dout, int it, int write_pred) {
    int b = blockIdx.x, tid = threadIdx.x;
    __shared__ float rmax[1024]; __shared__ int rid[1024]; __shared__ float rsum[1024];
    const float* lg = lg_all + (size_t)b * NV;
    float mx = -3.0e38f; int mi = 0;
    for (int i = tid; i < NV; i += 1024) {
        float v = lg[i];
        if (v > mx) { mx = v; mi = i; }
    }
    rmax[tid] = mx; rid[tid] = mi;
    __syncthreads();
    for (int st = 512; st > 0; st >>= 1) {
        if (tid < st) {
            float a = rmax[tid], c = rmax[tid+st];
            if (c > a || (c == a && rid[tid+st] < rid[tid])) { rmax[tid] = c; rid[tid] = rid[tid+st]; }
        }
        __syncthreads();
    }
    float gmx = rmax[0]; int gidx = rid[0];
    float s = 0.f;
    for (int i = tid; i < NV; i += 1024) s += expf(lg[i] - gmx);
    rsum[tid] = s; __syncthreads();
    for (int st = 512; st > 0; st >>= 1) {
        if (tid < st) rsum[tid] += rsum[tid+st];
        __syncthreads();
    }
    float inv = 1.f / rsum[0];
    float* pd = dout + ((size_t)b * NT + it) * NV;
    for (int i = tid; i < NV; i += 1024) pd[i] = expf(lg[i] - gmx) * inv;
    if (write_pred && tid == 0)
        dout[(size_t)NB*NT*NV + (size_t)b*NT + it] = (gidx == 0) ? 1.0f : 0.0f;
}

// split-K probs@emb: grid = 4 colblocks x 64 ksplits; writes partials (deterministic)
__global__ void __launch_bounds__(128) backproj_kernel(
    const float* __restrict__ dout, int it, const float* __restrict__ emb,
    float* __restrict__ part) {
    int tid = threadIdx.x;
    int cb = blockIdx.x & 3;
    int ks = blockIdx.x >> 2;
    int n = cb * 128 + tid;
    int k0 = ks * 502;              // 502 * 64 = 32128
    const float* p0 = dout + ((size_t)0*NT + it) * NV;
    const float* p1 = dout + ((size_t)1*NT + it) * NV;
    const float* p2 = dout + ((size_t)2*NT + it) * NV;
    const float* p3 = dout + ((size_t)3*NT + it) * NV;
    float a0=0,a1=0,a2=0,a3=0;
    for (int k = k0; k < k0 + 502; k++) {
        float ev = emb[(size_t)k * DM + n];
        a0 = fmaf(p0[k], ev, a0); a1 = fmaf(p1[k], ev, a1);
        a2 = fmaf(p2[k], ev, a2); a3 = fmaf(p3[k], ev, a3);
    }
    part[((size_t)ks*NB + 0)*DM + n] = a0;
    part[((size_t)ks*NB + 1)*DM + n] = a1;
    part[((size_t)ks*NB + 2)*DM + n] = a2;
    part[((size_t)ks*NB + 3)*DM + n] = a3;
}

__global__ void reduce_ye_kernel(const float* __restrict__ part, float* __restrict__ dst) {
    int i = blockIdx.x * blockDim.x + threadIdx.x; // 0..2047
    float s = 0.f;
    for (int ks = 0; ks < 64; ks++) s += part[(size_t)ks*NB*DM + i];
    dst[i] = s;
}

// ------------------------- host launch ------------------------------------

extern "C" void kernel_launch(void* const* d_in, const int* in_sizes, int n_in,
                              void* d_out, int out_size) {
    const int*   ids   = (const int*)  d_in[0];
    const float* maskp = (const float*)d_in[1];
    const float* emb   = (const float*)d_in[2];
    const float* enc_wq = (const float*)d_in[3];
    const float* enc_wk = (const float*)d_in[4];
    const float* enc_wv = (const float*)d_in[5];
    const float* enc_wo = (const float*)d_in[6];
    const float* enc_ln1= (const float*)d_in[7];
    const float* enc_w1 = (const float*)d_in[8];
    const float* enc_w2 = (const float*)d_in[9];
    const float* enc_ln2= (const float*)d_in[10];
    const float* enc_lnf= (const float*)d_in[11];
    const float* dec_sq = (const float*)d_in[12];
    const float* dec_sk = (const float*)d_in[13];
    const float* dec_sv = (const float*)d_in[14];
    const float* dec_so = (const float*)d_in[15];
    const float* dec_ln1= (const float*)d_in[16];
    const float* dec_cq = (const float*)d_in[17];
    const float* dec_ck = (const float*)d_in[18];
    const float* dec_cv = (const float*)d_in[19];
    const float* dec_co = (const float*)d_in[20];
    const float* dec_ln2= (const float*)d_in[21];
    const float* dec_w1 = (const float*)d_in[22];
    const float* dec_w2 = (const float*)d_in[23];
    const float* dec_ln3= (const float*)d_in[24];
    const float* dec_lnf= (const float*)d_in[25];
    const float* lm_head= (const float*)d_in[26];
    float* out = (float*)d_out;

    float *x,*h,*q,*k,*v,*att,*f,*hs,*ck,*cv,*sk,*sv,*ye,*xd,*qd,*ad,*fd,*lg,*part;
    cudaGetSymbolAddress((void**)&x,   g_x);
    cudaGetSymbolAddress((void**)&h,   g_h);
    cudaGetSymbolAddress((void**)&q,   g_q);
    cudaGetSymbolAddress((void**)&k,   g_k);
    cudaGetSymbolAddress((void**)&v,   g_v);
    cudaGetSymbolAddress((void**)&att, g_att);
    cudaGetSymbolAddress((void**)&f,   g_f);
    cudaGetSymbolAddress((void**)&hs,  g_hs);
    cudaGetSymbolAddress((void**)&ck,  g_ck);
    cudaGetSymbolAddress((void**)&cv,  g_cv);
    cudaGetSymbolAddress((void**)&sk,  g_sk);
    cudaGetSymbolAddress((void**)&sv,  g_sv);
    cudaGetSymbolAddress((void**)&ye,  g_ye);
    cudaGetSymbolAddress((void**)&xd,  g_xd);
    cudaGetSymbolAddress((void**)&qd,  g_qd);
    cudaGetSymbolAddress((void**)&ad,  g_ad);
    cudaGetSymbolAddress((void**)&fd,  g_fd);
    cudaGetSymbolAddress((void**)&lg,  g_logits);
    cudaGetSymbolAddress((void**)&part,g_part);

    const int M = NB*SS; // 256 encoder rows
    dim3 g1(DM/128, M/16);   // N=512 GEMMs
    dim3 g2(FF/128, M/16);   // N=2048 GEMMs

    // ---------------- encoder (once) ----------------
    embed_kernel<<<M,128>>>(ids, emb, x);
    init_y0_kernel<<<NB,128>>>(emb, ye);
    for (int l = 0; l < NL; l++) {
        rmsnorm_kernel<<<M,256>>>(x, enc_ln1 + (size_t)l*DM, h);
        gemm_kernel<<<g1,128>>>(h, enc_wq + (size_t)l*DM*DM, q, M, DM, DM, 0);
        gemm_kernel<<<g1,128>>>(h, enc_wk + (size_t)l*DM*DM, k, M, DM, DM, 0);
        gemm_kernel<<<g1,128>>>(h, enc_wv + (size_t)l*DM*DM, v, M, DM, DM, 0);
        attn_kernel<<<M*NH,64>>>(q, k, v, att, SS, SS, (long long)SS*DM, (long long)DM, maskp);
        gemm_kernel<<<g1,128>>>(att, enc_wo + (size_t)l*DM*DM, x, M, DM, DM, 2);
        rmsnorm_kernel<<<M,256>>>(x, enc_ln2 + (size_t)l*DM, h);
        gemm_kernel<<<g2,128>>>(h, enc_w1 + (size_t)l*DM*FF, f, M, FF, DM, 1);
        gemm_kernel<<<g1,128>>>(f, enc_w2 + (size_t)l*FF*DM, x, M, DM, FF, 2);
    }
    rmsnorm_kernel<<<M,256>>>(x, enc_lnf, hs);
    // cross-attn K/V cache (iteration-invariant)
    for (int l = 0; l < NL; l++) {
        gemm_kernel<<<g1,128>>>(hs, dec_ck + (size_t)l*DM*DM, ck + (size_t)l*NB*SS*DM, M, DM, DM, 0);
        gemm_kernel<<<g1,128>>>(hs, dec_cv + (size_t)l*DM*DM, cv + (size_t)l*NB*SS*DM, M, DM, DM, 0);
    }

    // ---------------- decoder (16 incremental steps, KV-cached) -----------
    size_t sm512  = (size_t)4*DM*sizeof(float);  // 8 KB
    size_t sm2048 = (size_t)4*FF*sizeof(float);  // 32 KB
    int write_pred = (out_size > NB*NT*NV) ? 1 : 0;

    for (int it = 0; it < NT; it++) {
        int p = it, t = it + 1;
        copyrow_kernel<<<16,128>>>(ye + (size_t)p*NB*DM, xd);
        for (int l = 0; l < NL; l++) {
            const float* ln1 = dec_ln1 + (size_t)l*DM;
            // self-attn qkv (k,v written straight into cache slot [l][p])
            gemv_kernel<<<4,128,sm512>>>(xd, dec_sq + (size_t)l*DM*DM, qd, DM, DM, ln1, 0);
            gemv_kernel<<<4,128,sm512>>>(xd, dec_sk + (size_t)l*DM*DM,
                                         sk + ((size_t)l*(NT+1)+p)*NB*DM, DM, DM, ln1, 0);
            gemv_kernel<<<4,128,sm512>>>(xd, dec_sv + (size_t)l*DM*DM,
                                         sv + ((size_t)l*(NT+1)+p)*NB*DM, DM, DM, ln1, 0);
            attn_kernel<<<NB*NH,64>>>(qd, sk + (size_t)l*(NT+1)*NB*DM,
                                      sv + (size_t)l*(NT+1)*NB*DM, ad,
                                      1, t, (long long)DM, (long long)NB*DM, nullptr);
            gemv_kernel<<<4,128,sm512>>>(ad, dec_so + (size_t)l*DM*DM, xd, DM, DM, nullptr, 2);
            // cross-attn
            gemv_kernel<<<4,128,sm512>>>(xd, dec_cq + (size_t)l*DM*DM, qd, DM, DM,
                                         dec_ln2 + (size_t)l*DM, 0);
            attn_kernel<<<NB*NH,64>>>(qd, ck + (size_t)l*NB*SS*DM, cv + (size_t)l*NB*SS*DM, ad,
                                      1, SS, (long long)SS*DM, (long long)DM, maskp);
            gemv_kernel<<<4,128,sm512>>>(ad, dec_co + (size_t)l*DM*DM, xd, DM, DM, nullptr, 2);
            // FFN
            gemv_kernel<<<FF/128,128,sm512>>>(xd, dec_w1 + (size_t)l*DM*FF, fd, FF, DM,
                                              dec_ln3 + (size_t)l*DM, 1);
            gemv_kernel<<<4,128,sm2048>>>(fd, dec_w2 + (size_t)l*FF*DM, xd, DM, FF, nullptr, 2);
        }
        // lm head (rms fused), softmax+argmax, soft-embedding for next step
        gemv_kernel<<<NV/128,128,sm512>>>(xd, lm_head, lg, NV, DM, dec_lnf, 0);
        softmax_kernel<<<NB,1024>>>(lg, out, it, write_pred);
        backproj_kernel<<<256,128>>>(out, it, emb, part);
        reduce_ye_kernel<<<16,128>>>(part, ye + (size_t)t*NB*DM);
    }
}

// round 2
// speedup vs baseline: 2.8061x; 2.8061x over previous
#include <cuda_runtime.h>
#include <math.h>

#define NB 4
#define SS 64
#define DM 512
#define NH 8
#define DHD 64
#define FF 2048
#define NL 2
#define NV 32128
#define NT 16
#define NEGB (-1e9f)

// ---------------- device scratch (static, no allocs) ----------------------
static __device__ float g_x[NB*SS*DM];
static __device__ float g_h[NB*SS*DM];
static __device__ float g_q[NB*SS*DM];
static __device__ float g_k[NB*SS*DM];
static __device__ float g_v[NB*SS*DM];
static __device__ float g_att[NB*SS*DM];
static __device__ float g_f[NB*SS*FF];
static __device__ float g_hs[NB*SS*DM];
static __device__ float g_ck[NL*NB*SS*DM];     // cross K cache [L][B][S][D]
static __device__ float g_cv[NL*NB*SS*DM];
static __device__ float g_sk[NL*(NT+1)*NB*DM]; // self K cache [L][T][B][D]
static __device__ float g_sv[NL*(NT+1)*NB*DM];
static __device__ float g_ye[(NT+1)*NB*DM];    // soft-embedding history [T][B][D]
static __device__ float g_xd[NB*DM];
static __device__ float g_qd[NB*DM];
static __device__ float g_ad[NB*DM];
static __device__ float g_fd[NB*FF];
static __device__ float g_lg[NB*NV];
static __device__ float g_part[16*NB*DM];      // backproj partials [16][B][D]
static __device__ unsigned g_cnt = 0;
static __device__ unsigned g_gen = 0;

struct P {
  const int* ids; const float* mask; const float* emb;
  const float *ewq,*ewk,*ewv,*ewo,*eln1,*ew1,*ew2,*eln2,*elnf;
  const float *dsq,*dsk,*dsv,*dso,*dln1;
  const float *dcq,*dck,*dcv,*dco,*dln2;
  const float *dw1,*dw2,*dln3,*dlnf,*lm;
  float* out; int wp;
};

// ---------------- grid barrier (release/acquire, generation-based) --------
__device__ __forceinline__ unsigned atom_inc_acqrel(unsigned* p) {
  unsigned o;
  asm volatile("atom.add.acq_rel.gpu.u32 %0, [%1], 1;" : "=r"(o) : "l"(p) : "memory");
  return o;
}
__device__ __forceinline__ unsigned ld_acq(unsigned* p) {
  unsigned v;
  asm volatile("ld.acquire.gpu.u32 %0, [%1];" : "=r"(v) : "l"(p) : "memory");
  return v;
}
__device__ __forceinline__ void st_rel(unsigned* p, unsigned v) {
  asm volatile("st.release.gpu.u32 [%0], %1;" :: "l"(p), "r"(v) : "memory");
}
__device__ __forceinline__ void gbar(int nb, unsigned* sg) {
  __syncthreads();
  if (threadIdx.x == 0) {
    unsigned target = *sg + 1u;
    unsigned prev = atom_inc_acqrel(&g_cnt);
    if (prev == (unsigned)nb - 1u) {
      g_cnt = 0;                     // ordered before release below
      st_rel(&g_gen, target);
    } else {
      while ((int)(ld_acq(&g_gen) - target) < 0) __nanosleep(64);
    }
    *sg = target;
  }
  __syncthreads();
}

// ---------------- phases ---------------------------------------------------

__device__ void ph_embed(const P& p, int bid, int nb, int tid) {
  for (int r = bid; r < NB*SS; r += nb) {
    int id = p.ids[r];
    const float4* s = (const float4*)(p.emb + (size_t)id*DM);
    float4* d = (float4*)(g_x + (size_t)r*DM);
    for (int i = tid; i < DM/4; i += 256) d[i] = s[i];
  }
  if (bid == nb-1) { // y0 = pad embedding (row 0) for all 4 batches
    for (int i = tid; i < NB*DM; i += 256) g_ye[i] = p.emb[i & (DM-1)];
  }
}

__device__ void ph_rms(const float* x, const float* ln, float* o, int rows,
                       float* sr, int bid, int nb, int tid) {
  for (int r = bid; r < rows; r += nb) {
    const float* xr = x + (size_t)r*DM;
    float s = 0.f;
    for (int i = tid; i < DM; i += 256) { float v = xr[i]; s += v*v; }
    sr[tid] = s; __syncthreads();
    for (int st = 128; st; st >>= 1) { if (tid < st) sr[tid] += sr[tid+st]; __syncthreads(); }
    float sc = rsqrtf(sr[0]*(1.f/DM) + 1e-6f);
    __syncthreads();
    float* orow = o + (size_t)r*DM;
    for (int i = tid; i < DM; i += 256) orow[i] = xr[i]*sc*ln[i];
  }
}

// encoder GEMM: tile 64 cols x 16 rows, thread = (col 0..63, rowgroup 0..3)
__device__ void ph_gemm(const float* A, const float* W, float* C,
                        int M, int N, int K, int flags,
                        float* sx, int bid, int nb, int tid) {
  int ntile = N >> 6, mtile = M >> 4;
  int ntasks = ntile*mtile;
  if (bid >= ntasks) return;
  int c = tid & 63, mg = tid >> 6;
  for (int t = bid; t < ntasks; t += nb) {
    int n0 = (t % ntile) << 6, m0 = (t / ntile) << 4;
    float a0=0.f,a1=0.f,a2=0.f,a3=0.f;
    for (int k0 = 0; k0 < K; k0 += 512) {
      __syncthreads();
      for (int e = tid; e < 16*512; e += 256)
        sx[e] = A[(size_t)(m0 + (e >> 9))*K + k0 + (e & 511)];
      __syncthreads();
      const float* wp = W + (size_t)k0*N + n0 + c;
      const float* xr = sx + (size_t)(mg*4)*512;
      #pragma unroll 4
      for (int k = 0; k < 512; k++) {
        float w = wp[(size_t)k*N];
        a0 = fmaf(xr[k],      w, a0);
        a1 = fmaf(xr[512+k],  w, a1);
        a2 = fmaf(xr[1024+k], w, a2);
        a3 = fmaf(xr[1536+k], w, a3);
      }
    }
    float acc[4] = {a0,a1,a2,a3};
    #pragma unroll
    for (int r = 0; r < 4; r++) {
      float v = acc[r];
      if (flags & 1) v = fmaxf(v, 0.f);
      size_t o = (size_t)(m0 + mg*4 + r)*N + n0 + c;
      if (flags & 2) C[o] += v; else C[o] = v;
    }
  }
}

// attention: warp per (query row, head). Tk <= 64.
__device__ void ph_attn(const float* q, const float* kc, const float* vc, float* o,
                        int Tq, int Tk, long long kbs, long long kts,
                        const float* mask, int ntasks,
                        float* sr, int bid, int nb, int tid) {
  int wid = tid >> 5, lane = tid & 31;
  float* ws = sr + wid*128;
  for (int t = bid*8 + wid; t < ntasks; t += nb*8) {
    int h = t & 7, rq = t >> 3, b = rq / Tq;
    const float* qp = q + (size_t)rq*DM + h*DHD;
    ws[lane] = qp[lane]; ws[32+lane] = qp[32+lane];
    __syncwarp();
    float s0 = -3e38f, s1 = -3e38f;
    if (lane < Tk) {
      const float* kp = kc + (size_t)b*kbs + (size_t)lane*kts + h*DHD;
      float d = 0.f;
      #pragma unroll 8
      for (int i = 0; i < DHD; i++) d = fmaf(ws[i], kp[i], d);
      s0 = d*0.125f;
      if (mask) s0 += (1.f - mask[b*SS + lane])*NEGB;
    }
    if (lane+32 < Tk) {
      const float* kp = kc + (size_t)b*kbs + (size_t)(lane+32)*kts + h*DHD;
      float d = 0.f;
      #pragma unroll 8
      for (int i = 0; i < DHD; i++) d = fmaf(ws[i], kp[i], d);
      s1 = d*0.125f;
      if (mask) s1 += (1.f - mask[b*SS + lane+32])*NEGB;
    }
    float m = fmaxf(s0, s1);
    #pragma unroll
    for (int off = 16; off; off >>= 1) m = fmaxf(m, __shfl_xor_sync(0xffffffffu, m, off));
    float e0 = (lane < Tk)    ? expf(s0 - m) : 0.f;
    float e1 = (lane+32 < Tk) ? expf(s1 - m) : 0.f;
    float su = e0 + e1;
    #pragma unroll
    for (int off = 16; off; off >>= 1) su += __shfl_xor_sync(0xffffffffu, su, off);
    __syncwarp();
    ws[64+lane] = e0; ws[96+lane] = e1;
    __syncwarp();
    float inv = 1.f/su;
    float o0 = 0.f, o1 = 0.f;
    const float* vb = vc + (size_t)b*kbs + h*DHD;
    for (int j = 0; j < Tk; j++) {
      float pj = ws[64+j];
      const float* vp = vb + (size_t)j*kts;
      o0 = fmaf(pj, vp[lane], o0);
      o1 = fmaf(pj, vp[32+lane], o1);
    }
    float* op = o + (size_t)rq*DM + h*DHD;
    op[lane] = o0*inv; op[32+lane] = o1*inv;
    __syncwarp();
  }
}

// decode GEMV: M=4, optional fused RMSNorm, multi-weight, 8-way K-split/block
__device__ void ph_gemv(const float* x, const float* const* Ws, float* const* Os, int nW,
                        int N, int K, const float* ln, int flags,
                        float* sx, float* sr, int bid, int nb, int tid) {
  int ntile = N >> 5;
  int ntasks = nW * ntile;
  if (bid >= ntasks) return;
  float sc[4];
  for (int m = 0; m < 4; m++) {
    const float* xm = x + (size_t)m*K;
    float s = 0.f;
    for (int k = tid; k < K; k += 256) { float v = xm[k]; sx[m*K+k] = v; s += v*v; }
    if (ln) {
      sr[tid] = s; __syncthreads();
      for (int st = 128; st; st >>= 1) { if (tid < st) sr[tid] += sr[tid+st]; __syncthreads(); }
      sc[m] = rsqrtf(sr[0]*(1.f/K) + 1e-6f);
      __syncthreads();
    }
  }
  if (ln) {
    for (int k = tid; k < K; k += 256) {
      float lw = ln[k];
      #pragma unroll
      for (int m = 0; m < 4; m++) sx[m*K+k] *= sc[m]*lw;
    }
  }
  __syncthreads();
  int c = tid & 31, ks = tid >> 5;
  int KS = K >> 3;
  const float* x0 = sx + ks*KS;
  const float* x1 = x0 + K; const float* x2 = x1 + K; const float* x3 = x2 + K;
  for (int t = bid; t < ntasks; t += nb) {
    int wi = t / ntile, tn = t % ntile;
    int n = (tn << 5) + c;
    const float* wp = Ws[wi] + (size_t)(ks*KS)*N + n;
    float a0=0.f,a1=0.f,a2=0.f,a3=0.f;
    #pragma unroll 8
    for (int k = 0; k < KS; k++) {
      float w = wp[(size_t)k*N];
      a0 = fmaf(x0[k], w, a0); a1 = fmaf(x1[k], w, a1);
      a2 = fmaf(x2[k], w, a2); a3 = fmaf(x3[k], w, a3);
    }
    sr[tid] = a0; sr[256+tid] = a1; sr[512+tid] = a2; sr[768+tid] = a3;
    __syncthreads();
    if (ks == 0) {
      float* op = Os[wi];
      #pragma unroll
      for (int m = 0; m < 4; m++) {
        float v = 0.f;
        #pragma unroll
        for (int kk = 0; kk < 8; kk++) v += sr[m*256 + kk*32 + c];
        if (flags & 1) v = fmaxf(v, 0.f);
        size_t oo = (size_t)m*N + n;
        if (flags & 2) op[oo] += v; else op[oo] = v;
      }
    }
    __syncthreads();
  }
}

__device__ void ph_softmax(float* out, int it, int wp, float* sr, int bid, int nb, int tid) {
  float* rf = sr; int* ri = (int*)(sr + 256); float* rs = sr + 512;
  for (int b = bid; b < NB; b += nb) {
    const float* lg = g_lg + (size_t)b*NV;
    float mx = -3e38f; int mi = 0;
    for (int i = tid; i < NV; i += 256) {
      float v = lg[i];
      if (v > mx) { mx = v; mi = i; }
    }
    rf[tid] = mx; ri[tid] = mi; __syncthreads();
    for (int st = 128; st; st >>= 1) {
      if (tid < st) {
        float a = rf[tid], c2 = rf[tid+st];
        if (c2 > a || (c2 == a && ri[tid+st] < ri[tid])) { rf[tid] = c2; ri[tid] = ri[tid+st]; }
      }
      __syncthreads();
    }
    float gmx = rf[0]; int gi = ri[0];
    __syncthreads();
    float s = 0.f;
    for (int i = tid; i < NV; i += 256) s += expf(lg[i] - gmx);
    rs[tid] = s; __syncthreads();
    for (int st = 128; st; st >>= 1) { if (tid < st) rs[tid] += rs[tid+st]; __syncthreads(); }
    float inv = 1.f/rs[0];
    __syncthreads();
    float* pd = out + ((size_t)b*NT + it)*NV;
    for (int i = tid; i < NV; i += 256) pd[i] = expf(lg[i] - gmx)*inv;
    if (wp && tid == 0) out[(size_t)NB*NT*NV + (size_t)b*NT + it] = (gi == 0) ? 1.f : 0.f;
  }
}

// probs @ emb, split-K partials: 16 colchunks(32) x 16 ksplits(2008)
__device__ void ph_backproj(const float* probs0, const float* emb,
                            float* sr, int bid, int nb, int tid) {
  const int KC = NV/16, KC8 = KC/8;    // 2008, 251
  int c = tid & 31, ks = tid >> 5;
  for (int t = bid; t < 256; t += nb) {
    int nc = t & 15, kc = t >> 4;
    int n = (nc << 5) + c;
    int kb = kc*KC + ks*KC8;
    const float* p0 = probs0;
    const float* p1 = probs0 + (size_t)NT*NV;
    const float* p2 = p1 + (size_t)NT*NV;
    const float* p3 = p2 + (size_t)NT*NV;
    float a0=0.f,a1=0.f,a2=0.f,a3=0.f;
    for (int k = kb; k < kb + KC8; k++) {
      float ev = emb[(size_t)k*DM + n];
      a0 = fmaf(p0[k], ev, a0); a1 = fmaf(p1[k], ev, a1);
      a2 = fmaf(p2[k], ev, a2); a3 = fmaf(p3[k], ev, a3);
    }
    sr[tid] = a0; sr[256+tid] = a1; sr[512+tid] = a2; sr[768+tid] = a3;
    __syncthreads();
    if (ks == 0) {
      #pragma unroll
      for (int m = 0; m < 4; m++) {
        float v = 0.f;
        #pragma unroll
        for (int kk = 0; kk < 8; kk++) v += sr[m*256 + kk*32 + c];
        g_part[(size_t)kc*(NB*DM) + (size_t)m*DM + n] = v;
      }
    }
    __syncthreads();
  }
}

__device__ void ph_redye(float* dst, int bid, int nb, int tid) {
  for (int e = bid*256 + tid; e < NB*DM; e += nb*256) {
    float s = 0.f;
    #pragma unroll
    for (int kc = 0; kc < 16; kc++) s += g_part[(size_t)kc*(NB*DM) + e];
    dst[e] = s;
  }
}

// ---------------- the megakernel ------------------------------------------
__global__ void __launch_bounds__(256) mega(P p, int nb) {
  __shared__ float sx[4*FF];     // 32 KB staging
  __shared__ float sr[1024];     // 4 KB reduce / attn scratch
  __shared__ unsigned sg;
  int tid = threadIdx.x, bid = blockIdx.x;
  if (tid == 0) sg = ld_acq(&g_gen);
  __syncthreads();

  // ---------------- encoder ----------------
  ph_embed(p, bid, nb, tid);                                       gbar(nb,&sg);
  for (int l = 0; l < NL; l++) {
    size_t o2 = (size_t)l*DM*DM, of = (size_t)l*DM*FF;
    ph_rms(g_x, p.eln1 + (size_t)l*DM, g_h, NB*SS, sr, bid, nb, tid); gbar(nb,&sg);
    ph_gemm(g_h, p.ewq + o2, g_q, NB*SS, DM, DM, 0, sx, bid, nb, tid);
    ph_gemm(g_h, p.ewk + o2, g_k, NB*SS, DM, DM, 0, sx, bid, nb, tid);
    ph_gemm(g_h, p.ewv + o2, g_v, NB*SS, DM, DM, 0, sx, bid, nb, tid); gbar(nb,&sg);
    ph_attn(g_q, g_k, g_v, g_att, SS, SS, (long long)SS*DM, (long long)DM,
            p.mask, NB*SS*NH, sr, bid, nb, tid);                      gbar(nb,&sg);
    ph_gemm(g_att, p.ewo + o2, g_x, NB*SS, DM, DM, 2, sx, bid, nb, tid); gbar(nb,&sg);
    ph_rms(g_x, p.eln2 + (size_t)l*DM, g_h, NB*SS, sr, bid, nb, tid); gbar(nb,&sg);
    ph_gemm(g_h, p.ew1 + of, g_f, NB*SS, FF, DM, 1, sx, bid, nb, tid); gbar(nb,&sg);
    ph_gemm(g_f, p.ew2 + of, g_x, NB*SS, DM, FF, 2, sx, bid, nb, tid); gbar(nb,&sg);
  }
  ph_rms(g_x, p.elnf, g_hs, NB*SS, sr, bid, nb, tid);                 gbar(nb,&sg);
  for (int l = 0; l < NL; l++) {
    ph_gemm(g_hs, p.dck + (size_t)l*DM*DM, g_ck + (size_t)l*NB*SS*DM,
            NB*SS, DM, DM, 0, sx, bid, nb, tid);
    ph_gemm(g_hs, p.dcv + (size_t)l*DM*DM, g_cv + (size_t)l*NB*SS*DM,
            NB*SS, DM, DM, 0, sx, bid, nb, tid);
  }
  gbar(nb,&sg);

  // ---------------- decoder: 16 incremental KV-cached steps ----------------
  for (int it = 0; it < NT; it++) {
    const float* xin = g_ye + (size_t)it*NB*DM;
    if (bid == nb-1)  // residual base for this step (runs concurrently with qkv)
      for (int e = tid; e < NB*DM; e += 256) g_xd[e] = xin[e];
    for (int l = 0; l < NL; l++) {
      size_t o2 = (size_t)l*DM*DM, of = (size_t)l*DM*FF;
      const float* lx = (l == 0) ? xin : g_xd;
      {
        const float* Ws[3] = { p.dsq + o2, p.dsk + o2, p.dsv + o2 };
        float* Os[3] = { g_qd,
                         g_sk + ((size_t)l*(NT+1) + it)*NB*DM,
                         g_sv + ((size_t)l*(NT+1) + it)*NB*DM };
        ph_gemv(lx, Ws, Os, 3, DM, DM, p.dln1 + (size_t)l*DM, 0, sx, sr, bid, nb, tid);
      }
      gbar(nb,&sg);
      ph_attn(g_qd, g_sk + (size_t)l*(NT+1)*NB*DM, g_sv + (size_t)l*(NT+1)*NB*DM,
              g_ad, 1, it+1, (long long)DM, (long long)NB*DM, nullptr,
              NB*NH, sr, bid, nb, tid);
      gbar(nb,&sg);
      { const float* Ws[1] = { p.dso + o2 }; float* Os[1] = { g_xd };
        ph_gemv(g_ad, Ws, Os, 1, DM, DM, nullptr, 2, sx, sr, bid, nb, tid); }
      gbar(nb,&sg);
      { const float* Ws[1] = { p.dcq + o2 }; float* Os[1] = { g_qd };
        ph_gemv(g_xd, Ws, Os, 1, DM, DM, p.dln2 + (size_t)l*DM, 0, sx, sr, bid, nb, tid); }
      gbar(nb,&sg);
      ph_attn(g_qd, g_ck + (size_t)l*NB*SS*DM, g_cv + (size_t)l*NB*SS*DM,
              g_ad, 1, SS, (long long)SS*DM, (long long)DM, p.mask,
              NB*NH, sr, bid, nb, tid);
      gbar(nb,&sg);
      { const float* Ws[1] = { p.dco + o2 }; float* Os[1] = { g_xd };
        ph_gemv(g_ad, Ws, Os, 1, DM, DM, nullptr, 2, sx, sr, bid, nb, tid); }
      gbar(nb,&sg);
      { const float* Ws[1] = { p.dw1 + of }; float* Os[1] = { g_fd };
        ph_gemv(g_xd, Ws, Os, 1, FF, DM, p.dln3 + (size_t)l*DM, 1, sx, sr, bid, nb, tid); }
      gbar(nb,&sg);
      { const float* Ws[1] = { p.dw2 + of }; float* Os[1] = { g_xd };
        ph_gemv(g_fd, Ws, Os, 1, DM, FF, nullptr, 2, sx, sr, bid, nb, tid); }
      gbar(nb,&sg);
    }
    { const float* Ws[1] = { p.lm }; float* Os[1] = { g_lg };
      ph_gemv(g_xd, Ws, Os, 1, NV, DM, p.dlnf, 0, sx, sr, bid, nb, tid); }
    gbar(nb,&sg);
    ph_softmax(p.out, it, p.wp, sr, bid, nb, tid);
    gbar(nb,&sg);
    ph_backproj(p.out + (size_t)it*NV, p.emb, sr, bid, nb, tid);
    gbar(nb,&sg);
    ph_redye(g_ye + (size_t)(it+1)*NB*DM, bid, nb, tid);
    gbar(nb,&sg);
  }
}

// ---------------- host ------------------------------------------------------
extern "C" void kernel_launch(void* const* d_in, const int* in_sizes, int n_in,
                              void* d_out, int out_size) {
  P p;
  p.ids   = (const int*)  d_in[0];
  p.mask  = (const float*)d_in[1];
  p.emb   = (const float*)d_in[2];
  p.ewq   = (const float*)d_in[3];
  p.ewk   = (const float*)d_in[4];
  p.ewv   = (const float*)d_in[5];
  p.ewo   = (const float*)d_in[6];
  p.eln1  = (const float*)d_in[7];
  p.ew1   = (const float*)d_in[8];
  p.ew2   = (const float*)d_in[9];
  p.eln2  = (const float*)d_in[10];
  p.elnf  = (const float*)d_in[11];
  p.dsq   = (const float*)d_in[12];
  p.dsk   = (const float*)d_in[13];
  p.dsv   = (const float*)d_in[14];
  p.dso   = (const float*)d_in[15];
  p.dln1  = (const float*)d_in[16];
  p.dcq   = (const float*)d_in[17];
  p.dck   = (const float*)d_in[18];
  p.dcv   = (const float*)d_in[19];
  p.dco   = (const float*)d_in[20];
  p.dln2  = (const float*)d_in[21];
  p.dw1   = (const float*)d_in[22];
  p.dw2   = (const float*)d_in[23];
  p.dln3  = (const float*)d_in[24];
  p.dlnf  = (const float*)d_in[25];
  p.lm    = (const float*)d_in[26];
  p.out   = (float*)d_out;
  p.wp    = (out_size > NB*NT*NV) ? 1 : 0;

  int dev = 0; cudaGetDevice(&dev);
  int sms = 0; cudaDeviceGetAttribute(&sms, cudaDevAttrMultiProcessorCount, dev);
  int nb = sms;   // one resident block per SM -> safe hand-rolled grid barrier
  mega<<<nb, 256>>>(p, nb);
}

// round 3
// speedup vs baseline: 5.5664x; 1.9837x over previous
#include <cuda_runtime.h>
#include <math.h>

#define NB 4
#define SS 64
#define DM 512
#define NH 8
#define DHD 64
#define FF 2048
#define NL 2
#define NV 32128
#define NT 16
#define NEGB (-1e9f)

// ---------------- device scratch (static, no allocs) ----------------------
static __device__ float g_x[NB*SS*DM];
static __device__ float g_h[NB*SS*DM];
static __device__ float g_q[NB*SS*DM];
static __device__ float g_k[NB*SS*DM];
static __device__ float g_v[NB*SS*DM];
static __device__ float g_att[NB*SS*DM];
static __device__ float g_f[NB*SS*FF];
static __device__ float g_hs[NB*SS*DM];
static __device__ float g_gp[4*NB*SS*DM];       // encoder gemm K-split partials
static __device__ float g_ck[NL*NB*SS*DM];      // cross K cache [L][B][S][D]
static __device__ float g_cv[NL*NB*SS*DM];
static __device__ float g_sk[NL*(NT+1)*NB*DM];  // self K cache [L][T][B][D]
static __device__ float g_sv[NL*(NT+1)*NB*DM];
static __device__ float g_ye[(NT+1)*NB*DM];     // soft-embedding history
static __device__ float g_xd[NB*DM];
static __device__ float g_qd[NB*DM];
static __device__ float g_ad[NB*DM];
static __device__ float g_fd[NB*FF];
static __device__ float g_lg[NB*NV];
static __device__ float g_vp[8*4*DM];           // gemv block-ksplit partials
static __device__ float g_part[128*NB*DM];      // backproj partials [128][B][D]
static __device__ float g_pm[NB*16], g_ps[NB*16];
static __device__ int   g_pi[NB*16];
static __device__ unsigned g_cnt;               // monotonic barrier counter

struct P {
  const int* ids; const float* mask; const float* emb;
  const float *ewq,*ewk,*ewv,*ewo,*eln1,*ew1,*ew2,*eln2,*elnf;
  const float *dsq,*dsk,*dsv,*dso,*dln1;
  const float *dcq,*dck,*dcv,*dco,*dln2;
  const float *dw1,*dw2,*dln3,*dlnf,*lm;
  float* out; int wp;
};

// ---------------- grid barrier: monotonic count, red+acquire-poll ---------
__device__ __forceinline__ void gbar(int nb, unsigned* sgp) {
  __syncthreads();
  if (threadIdx.x == 0) {
    unsigned tgt = *sgp + (unsigned)nb;
    asm volatile("red.release.gpu.add.u32 [%0], 1;" :: "l"(&g_cnt) : "memory");
    unsigned v;
    do { asm volatile("ld.acquire.gpu.u32 %0, [%1];" : "=r"(v) : "l"(&g_cnt) : "memory"); }
    while ((int)(v - tgt) < 0);
    *sgp = tgt;
  }
  __syncthreads();
}

// ---------------- phases ---------------------------------------------------

__device__ void ph_embed(const P& p, int bid, int nb, int tid) {
  for (int r = bid; r < NB*SS; r += nb) {
    int id = p.ids[r];
    const float4* s = (const float4*)(p.emb + (size_t)id*DM);
    float4* d = (float4*)(g_x + (size_t)r*DM);
    for (int i = tid; i < DM/4; i += 256) d[i] = s[i];
  }
  if (bid == nb-1) {
    for (int i = tid; i < NB*DM; i += 256) g_ye[i] = p.emb[i & (DM-1)];
  }
}

__device__ void ph_rms(const float* x, const float* ln, float* o, int rows,
                       float* sr, int bid, int nb, int tid) {
  const float4* x4 = (const float4*)x;
  const float4* l4 = (const float4*)ln;
  float4* o4 = (float4*)o;
  for (int r = bid; r < rows; r += nb) {
    float s = 0.f;
    for (int i = tid; i < DM/4; i += 256) {
      float4 v = x4[(size_t)r*(DM/4)+i];
      s += v.x*v.x + v.y*v.y + v.z*v.z + v.w*v.w;
    }
    sr[tid] = s; __syncthreads();
    for (int st = 128; st; st >>= 1) { if (tid < st) sr[tid] += sr[tid+st]; __syncthreads(); }
    float sc = rsqrtf(sr[0]*(1.f/DM) + 1e-6f);
    __syncthreads();
    for (int i = tid; i < DM/4; i += 256) {
      float4 v = x4[(size_t)r*(DM/4)+i]; float4 lw = l4[i];
      v.x *= sc*lw.x; v.y *= sc*lw.y; v.z *= sc*lw.z; v.w *= sc*lw.w;
      o4[(size_t)r*(DM/4)+i] = v;
    }
  }
}

// encoder GEMM: 64x64 tile, 256 threads, 4x4 micro-tile, optional K-split
__device__ void ph_gemm(const float* A, const float* const* Ws, float* const* Cs, int nW,
                        int M, int N, int K, int flags, int ksp, float* Cpart,
                        float* sx, int bid, int nb, int tid) {
  int mt = M >> 6, nt = N >> 6;
  int per = mt*nt*ksp;
  int ntasks = nW*per;
  if (bid >= ntasks) return;
  float* As = sx;           // [16][64]
  float* Wt = sx + 1024;    // [16][64]
  int Klen = K / ksp;
  int tr = tid >> 4, tc = tid & 15;
  int arow = tid >> 2, akq = tid & 3;
  int wkk = tid >> 4, wcc = (tid & 15) << 2;
  for (int t = bid; t < ntasks; t += nb) {
    int wi = t / per, r = t % per;
    int kc = r / (mt*nt); int r2 = r % (mt*nt);
    int m0 = (r2 / nt) << 6, n0 = (r2 % nt) << 6;
    int kb = kc*Klen;
    const float* W = Ws[wi];
    float acc[4][4];
    #pragma unroll
    for (int i = 0; i < 4; i++)
      #pragma unroll
      for (int j = 0; j < 4; j++) acc[i][j] = 0.f;
    for (int kt = 0; kt < Klen; kt += 16) {
      __syncthreads();
      float4 av = *(const float4*)&A[(size_t)(m0+arow)*K + kb + kt + (akq<<2)];
      As[(akq*4+0)*64 + arow] = av.x;
      As[(akq*4+1)*64 + arow] = av.y;
      As[(akq*4+2)*64 + arow] = av.z;
      As[(akq*4+3)*64 + arow] = av.w;
      *(float4*)&Wt[wkk*64 + wcc] = *(const float4*)&W[(size_t)(kb+kt+wkk)*N + n0 + wcc];
      __syncthreads();
      #pragma unroll
      for (int kk = 0; kk < 16; kk++) {
        float4 a = *(const float4*)&As[kk*64 + (tr<<2)];
        float4 w = *(const float4*)&Wt[kk*64 + (tc<<2)];
        acc[0][0]=fmaf(a.x,w.x,acc[0][0]); acc[0][1]=fmaf(a.x,w.y,acc[0][1]);
        acc[0][2]=fmaf(a.x,w.z,acc[0][2]); acc[0][3]=fmaf(a.x,w.w,acc[0][3]);
        acc[1][0]=fmaf(a.y,w.x,acc[1][0]); acc[1][1]=fmaf(a.y,w.y,acc[1][1]);
        acc[1][2]=fmaf(a.y,w.z,acc[1][2]); acc[1][3]=fmaf(a.y,w.w,acc[1][3]);
        acc[2][0]=fmaf(a.z,w.x,acc[2][0]); acc[2][1]=fmaf(a.z,w.y,acc[2][1]);
        acc[2][2]=fmaf(a.z,w.z,acc[2][2]); acc[2][3]=fmaf(a.z,w.w,acc[2][3]);
        acc[3][0]=fmaf(a.w,w.x,acc[3][0]); acc[3][1]=fmaf(a.w,w.y,acc[3][1]);
        acc[3][2]=fmaf(a.w,w.z,acc[3][2]); acc[3][3]=fmaf(a.w,w.w,acc[3][3]);
      }
    }
    #pragma unroll
    for (int i = 0; i < 4; i++) {
      float4 v = make_float4(acc[i][0], acc[i][1], acc[i][2], acc[i][3]);
      if (ksp == 1) {
        if (flags & 1) { v.x=fmaxf(v.x,0.f); v.y=fmaxf(v.y,0.f); v.z=fmaxf(v.z,0.f); v.w=fmaxf(v.w,0.f); }
        float4* cp = (float4*)&Cs[wi][(size_t)(m0+(tr<<2)+i)*N + n0 + (tc<<2)];
        if (flags & 2) { float4 o = *cp; o.x+=v.x; o.y+=v.y; o.z+=v.z; o.w+=v.w; *cp = o; }
        else *cp = v;
      } else {
        *(float4*)&Cpart[((size_t)kc*M + m0+(tr<<2)+i)*N + n0 + (tc<<2)] = v;
      }
    }
  }
}

__device__ void ph_gred(float* C, const float* part, int M, int N, int ksp, int flags,
                        int bid, int nb, int tid) {
  int tot = (M*N) >> 2;
  const float4* p4 = (const float4*)part;
  float4* c4 = (float4*)C;
  for (int i = bid*256+tid; i < tot; i += nb*256) {
    float4 v = p4[i];
    for (int kc = 1; kc < ksp; kc++) {
      float4 u = p4[(size_t)kc*tot + i];
      v.x += u.x; v.y += u.y; v.z += u.z; v.w += u.w;
    }
    if (flags & 1) { v.x=fmaxf(v.x,0.f); v.y=fmaxf(v.y,0.f); v.z=fmaxf(v.z,0.f); v.w=fmaxf(v.w,0.f); }
    if (flags & 2) { float4 o = c4[i]; o.x+=v.x; o.y+=v.y; o.z+=v.z; o.w+=v.w; c4[i] = o; }
    else c4[i] = v;
  }
}

// attention: warp per (query row, head). Tk <= 64.
__device__ void ph_attn(const float* q, const float* kc, const float* vc, float* o,
                        int Tq, int Tk, long long kbs, long long kts,
                        const float* mask, int ntasks,
                        float* sr, int bid, int nb, int tid) {
  int wid = tid >> 5, lane = tid & 31;
  float* ws = sr + wid*128;
  for (int t = bid*8 + wid; t < ntasks; t += nb*8) {
    int h = t & 7, rq = t >> 3, b = rq / Tq;
    const float* qp = q + (size_t)rq*DM + h*DHD;
    ws[lane] = qp[lane]; ws[32+lane] = qp[32+lane];
    __syncwarp();
    float s0 = -3e38f, s1 = -3e38f;
    if (lane < Tk) {
      const float* kp = kc + (size_t)b*kbs + (size_t)lane*kts + h*DHD;
      float d = 0.f;
      #pragma unroll 8
      for (int i = 0; i < DHD; i++) d = fmaf(ws[i], kp[i], d);
      s0 = d*0.125f;
      if (mask) s0 += (1.f - mask[b*SS + lane])*NEGB;
    }
    if (lane+32 < Tk) {
      const float* kp = kc + (size_t)b*kbs + (size_t)(lane+32)*kts + h*DHD;
      float d = 0.f;
      #pragma unroll 8
      for (int i = 0; i < DHD; i++) d = fmaf(ws[i], kp[i], d);
      s1 = d*0.125f;
      if (mask) s1 += (1.f - mask[b*SS + lane+32])*NEGB;
    }
    float m = fmaxf(s0, s1);
    #pragma unroll
    for (int off = 16; off; off >>= 1) m = fmaxf(m, __shfl_xor_sync(0xffffffffu, m, off));
    float e0 = (lane < Tk)    ? expf(s0 - m) : 0.f;
    float e1 = (lane+32 < Tk) ? expf(s1 - m) : 0.f;
    float su = e0 + e1;
    #pragma unroll
    for (int off = 16; off; off >>= 1) su += __shfl_xor_sync(0xffffffffu, su, off);
    __syncwarp();
    ws[64+lane] = e0; ws[96+lane] = e1;
    __syncwarp();
    float inv = 1.f/su;
    float o0 = 0.f, o1 = 0.f;
    const float* vb = vc + (size_t)b*kbs + h*DHD;
    for (int j = 0; j < Tk; j++) {
      float pj = ws[64+j];
      const float* vp = vb + (size_t)j*kts;
      o0 = fmaf(pj, vp[lane], o0);
      o1 = fmaf(pj, vp[32+lane], o1);
    }
    float* op = o + (size_t)rq*DM + h*DHD;
    op[lane] = o0*inv; op[32+lane] = o1*inv;
    __syncwarp();
  }
}

// decode GEMV: M=4 rows, float4 weights, 128-col tiles, 8-way in-block K-split
__device__ void ph_gemv(const float* x, const float* const* Ws, float* const* Os, int nW,
                        int N, int K, const float* ln, int flags,
                        float* sx, float* sr, int bid, int nb, int tid) {
  int ntile = N >> 7;
  int ntasks = nW * ntile;
  if (bid >= ntasks) return;
  int K4 = K >> 2;
  const float4* x4 = (const float4*)x;
  float4* sx4 = (float4*)sx;
  float s[4];
  #pragma unroll
  for (int m = 0; m < 4; m++) {
    float acc = 0.f;
    for (int i = tid; i < K4; i += 256) {
      float4 v = x4[m*K4+i]; sx4[m*K4+i] = v;
      acc += v.x*v.x + v.y*v.y + v.z*v.z + v.w*v.w;
    }
    s[m] = acc;
  }
  if (ln) {
    #pragma unroll
    for (int m = 0; m < 4; m++) sr[m*256+tid] = s[m];
    __syncthreads();
    for (int st = 128; st; st >>= 1) {
      if (tid < st)
        #pragma unroll
        for (int m = 0; m < 4; m++) sr[m*256+tid] += sr[m*256+tid+st];
      __syncthreads();
    }
    float sc[4];
    #pragma unroll
    for (int m = 0; m < 4; m++) sc[m] = rsqrtf(sr[m*256]*(1.f/K) + 1e-6f);
    __syncthreads();
    const float4* ln4 = (const float4*)ln;
    for (int i = tid; i < K4; i += 256) {
      float4 lw = ln4[i];
      #pragma unroll
      for (int m = 0; m < 4; m++) {
        float4 v = sx4[m*K4+i];
        v.x *= sc[m]*lw.x; v.y *= sc[m]*lw.y; v.z *= sc[m]*lw.z; v.w *= sc[m]*lw.w;
        sx4[m*K4+i] = v;
      }
    }
  }
  __syncthreads();
  int c = tid & 31, ks = tid >> 5;
  int KS = K >> 3;
  const float* xb = sx + ks*KS;
  int N4 = N >> 2;
  float4* sr4 = (float4*)sr;
  for (int t = bid; t < ntasks; t += nb) {
    int wi = t / ntile, tn = t % ntile;
    const float4* wp = (const float4*)Ws[wi] + (size_t)(ks*KS)*N4 + (tn*32 + c);
    float4 a0 = make_float4(0,0,0,0), a1 = a0, a2 = a0, a3 = a0;
    #pragma unroll 16
    for (int k = 0; k < KS; k++) {
      float4 w = wp[(size_t)k*N4];
      float v0 = xb[k], v1 = xb[K+k], v2 = xb[2*K+k], v3 = xb[3*K+k];
      a0.x=fmaf(v0,w.x,a0.x); a0.y=fmaf(v0,w.y,a0.y); a0.z=fmaf(v0,w.z,a0.z); a0.w=fmaf(v0,w.w,a0.w);
      a1.x=fmaf(v1,w.x,a1.x); a1.y=fmaf(v1,w.y,a1.y); a1.z=fmaf(v1,w.z,a1.z); a1.w=fmaf(v1,w.w,a1.w);
      a2.x=fmaf(v2,w.x,a2.x); a2.y=fmaf(v2,w.y,a2.y); a2.z=fmaf(v2,w.z,a2.z); a2.w=fmaf(v2,w.w,a2.w);
      a3.x=fmaf(v3,w.x,a3.x); a3.y=fmaf(v3,w.y,a3.y); a3.z=fmaf(v3,w.z,a3.z); a3.w=fmaf(v3,w.w,a3.w);
    }
    float4 am[4] = {a0, a1, a2, a3};
    #pragma unroll
    for (int m = 0; m < 4; m++) {
      sr4[tid] = am[m];
      __syncthreads();
      if (ks == 0) {
        float4 v = sr4[c];
        #pragma unroll
        for (int kk = 1; kk < 8; kk++) {
          float4 u = sr4[kk*32+c];
          v.x += u.x; v.y += u.y; v.z += u.z; v.w += u.w;
        }
        if (flags & 1) { v.x=fmaxf(v.x,0.f); v.y=fmaxf(v.y,0.f); v.z=fmaxf(v.z,0.f); v.w=fmaxf(v.w,0.f); }
        float4* op = (float4*)(Os[wi] + (size_t)m*N) + tn*32 + c;
        if (flags & 2) { float4 o = *op; o.x+=v.x; o.y+=v.y; o.z+=v.z; o.w+=v.w; *op = o; }
        else *op = v;
      }
      __syncthreads();
    }
  }
}

// GEMV with block-level K-split (no ln), writes partials; single task per block
__device__ void ph_gemv_ks(const float* x, const float* W, int N, int K, int bksp,
                           float* part, float* sx, float* sr, int bid, int nb, int tid) {
  int ntile = N >> 7;
  int ntasks = ntile * bksp;
  if (bid >= ntasks) return;
  int bk = bid / ntile, tn = bid % ntile;
  int Klen = K / bksp, kb = bk*Klen;
  const float4* x4 = (const float4*)x;
  float4* sx4 = (float4*)sx;
  int KL4 = Klen >> 2;
  for (int i = tid; i < KL4; i += 256) {
    #pragma unroll
    for (int m = 0; m < 4; m++) sx4[m*KL4+i] = x4[(size_t)m*(K>>2) + (kb>>2) + i];
  }
  __syncthreads();
  int c = tid & 31, ks = tid >> 5;
  int KS = Klen >> 3;
  const float* xb = sx + ks*KS;
  int N4 = N >> 2;
  const float4* wp = (const float4*)W + (size_t)(kb + ks*KS)*N4 + (tn*32 + c);
  float4 a0 = make_float4(0,0,0,0), a1 = a0, a2 = a0, a3 = a0;
  #pragma unroll 16
  for (int k = 0; k < KS; k++) {
    float4 w = wp[(size_t)k*N4];
    float v0 = xb[k], v1 = xb[Klen+k], v2 = xb[2*Klen+k], v3 = xb[3*Klen+k];
    a0.x=fmaf(v0,w.x,a0.x); a0.y=fmaf(v0,w.y,a0.y); a0.z=fmaf(v0,w.z,a0.z); a0.w=fmaf(v0,w.w,a0.w);
    a1.x=fmaf(v1,w.x,a1.x); a1.y=fmaf(v1,w.y,a1.y); a1.z=fmaf(v1,w.z,a1.z); a1.w=fmaf(v1,w.w,a1.w);
    a2.x=fmaf(v2,w.x,a2.x); a2.y=fmaf(v2,w.y,a2.y); a2.z=fmaf(v2,w.z,a2.z); a2.w=fmaf(v2,w.w,a2.w);
    a3.x=fmaf(v3,w.x,a3.x); a3.y=fmaf(v3,w.y,a3.y); a3.z=fmaf(v3,w.z,a3.z); a3.w=fmaf(v3,w.w,a3.w);
  }
  float4 am[4] = {a0, a1, a2, a3};
  float4* sr4 = (float4*)sr;
  #pragma unroll
  for (int m = 0; m < 4; m++) {
    sr4[tid] = am[m];
    __syncthreads();
    if (ks == 0) {
      float4 v = sr4[c];
      #pragma unroll
      for (int kk = 1; kk < 8; kk++) {
        float4 u = sr4[kk*32+c];
        v.x += u.x; v.y += u.y; v.z += u.z; v.w += u.w;
      }
      *((float4*)(part + ((size_t)bk*4 + m)*N) + tn*32 + c) = v;
    }
    __syncthreads();
  }
}

__device__ void ph_vred(float* O, const float* part, int bksp, int N, int flags,
                        int bid, int nb, int tid) {
  int tot = N;  // float4 count over [4][N/4]
  const float4* p4 = (const float4*)part;
  float4* o4 = (float4*)O;
  for (int i = bid*256+tid; i < tot; i += nb*256) {
    float4 v = p4[i];
    for (int bk = 1; bk < bksp; bk++) {
      float4 u = p4[(size_t)bk*N + i];
      v.x += u.x; v.y += u.y; v.z += u.z; v.w += u.w;
    }
    if (flags & 1) { v.x=fmaxf(v.x,0.f); v.y=fmaxf(v.y,0.f); v.z=fmaxf(v.z,0.f); v.w=fmaxf(v.w,0.f); }
    if (flags & 2) { float4 o = o4[i]; o.x+=v.x; o.y+=v.y; o.z+=v.z; o.w+=v.w; o4[i] = o; }
    else o4[i] = v;
  }
}

// softmax phase 1: per (batch, chunk) partial max/argmax/sum-exp
__device__ void ph_sm1(float* sr, int bid, int nb, int tid) {
  const int CL = NV/16;  // 2008
  int* si = (int*)(sr + 256);
  for (int t = bid; t < NB*16; t += nb) {
    int b = t >> 4, ch = t & 15;
    const float* lg = g_lg + (size_t)b*NV + ch*CL;
    float mx = -3e38f; int mi = 0;
    for (int i = tid; i < CL; i += 256) {
      float v = lg[i];
      if (v > mx) { mx = v; mi = i; }
    }
    sr[tid] = mx; si[tid] = mi;
    __syncthreads();
    for (int st = 128; st; st >>= 1) {
      if (tid < st) {
        float a = sr[tid], c2 = sr[tid+st];
        int ia = si[tid], ic = si[tid+st];
        if (c2 > a || (c2 == a && ic < ia)) { sr[tid] = c2; si[tid] = ic; }
      }
      __syncthreads();
    }
    float gm = sr[0]; int gi = si[0];
    __syncthreads();
    float s = 0.f;
    for (int i = tid; i < CL; i += 256) s += expf(lg[i] - gm);
    sr[tid] = s; __syncthreads();
    for (int st = 128; st; st >>= 1) { if (tid < st) sr[tid] += sr[tid+st]; __syncthreads(); }
    if (tid == 0) { g_pm[t] = gm; g_ps[t] = sr[0]; g_pi[t] = gi + ch*CL; }
    __syncthreads();
  }
}

// softmax phase 2: combine + write probs (+ pred flag)
__device__ void ph_sm2(const P& p, int it, int bid, int nb, int tid) {
  const int CL = NV/16;
  for (int t = bid; t < NB*16; t += nb) {
    int b = t >> 4, ch = t & 15;
    float M = -3e38f;
    #pragma unroll
    for (int i = 0; i < 16; i++) M = fmaxf(M, g_pm[b*16+i]);
    float S = 0.f; int gi = -1;
    #pragma unroll
    for (int i = 0; i < 16; i++) {
      float m = g_pm[b*16+i];
      S += g_ps[b*16+i]*expf(m - M);
      if (gi < 0 && m == M) gi = g_pi[b*16+i];
    }
    float inv = 1.f/S;
    const float* lg = g_lg + (size_t)b*NV + ch*CL;
    float* pd = p.out + ((size_t)b*NT + it)*NV + ch*CL;
    for (int i = tid; i < CL; i += 256) pd[i] = expf(lg[i] - M)*inv;
    if (ch == 0 && tid == 0 && p.wp)
      p.out[(size_t)NB*NT*NV + (size_t)b*NT + it] = (gi == 0) ? 1.f : 0.f;
  }
}

// probs @ emb: 128 K-chunk tasks (251 k each), 2-way in-block K-split
__device__ void ph_bp(const float* probs, const float* emb, float* sx,
                      int bid, int nb, int tid) {
  const int KC = NV/128;  // 251
  if (bid >= 128) return;
  int c = tid & 127, ks = tid >> 7;
  const float4* e4 = (const float4*)emb;
  const float* p0 = probs;
  const float* p1 = probs + (size_t)NT*NV;
  const float* p2 = p1 + (size_t)NT*NV;
  const float* p3 = p2 + (size_t)NT*NV;
  for (int t = bid; t < 128; t += nb) {
    int kb = t*KC + ks*126;
    int ke = t*KC + KC; if (kb + 126 < ke) ke = kb + 126;
    float4 a0 = make_float4(0,0,0,0), a1 = a0, a2 = a0, a3 = a0;
    #pragma unroll 8
    for (int k = kb; k < ke; k++) {
      float4 ev = e4[(size_t)k*128 + c];
      float q0 = p0[k], q1 = p1[k], q2 = p2[k], q3 = p3[k];
      a0.x=fmaf(q0,ev.x,a0.x); a0.y=fmaf(q0,ev.y,a0.y); a0.z=fmaf(q0,ev.z,a0.z); a0.w=fmaf(q0,ev.w,a0.w);
      a1.x=fmaf(q1,ev.x,a1.x); a1.y=fmaf(q1,ev.y,a1.y); a1.z=fmaf(q1,ev.z,a1.z); a1.w=fmaf(q1,ev.w,a1.w);
      a2.x=fmaf(q2,ev.x,a2.x); a2.y=fmaf(q2,ev.y,a2.y); a2.z=fmaf(q2,ev.z,a2.z); a2.w=fmaf(q2,ev.w,a2.w);
      a3.x=fmaf(q3,ev.x,a3.x); a3.y=fmaf(q3,ev.y,a3.y); a3.z=fmaf(q3,ev.z,a3.z); a3.w=fmaf(q3,ev.w,a3.w);
    }
    float4* s4 = (float4*)sx;
    if (ks == 1) { s4[c] = a0; s4[128+c] = a1; s4[256+c] = a2; s4[384+c] = a3; }
    __syncthreads();
    if (ks == 0) {
      float4* gp = (float4*)(g_part + (size_t)t*NB*DM);
      float4 u;
      u = s4[c];     a0.x+=u.x; a0.y+=u.y; a0.z+=u.z; a0.w+=u.w; gp[c]       = a0;
      u = s4[128+c]; a1.x+=u.x; a1.y+=u.y; a1.z+=u.z; a1.w+=u.w; gp[128+c]   = a1;
      u = s4[256+c]; a2.x+=u.x; a2.y+=u.y; a2.z+=u.z; a2.w+=u.w; gp[256+c]   = a2;
      u = s4[384+c]; a3.x+=u.x; a3.y+=u.y; a3.z+=u.z; a3.w+=u.w; gp[384+c]   = a3;
    }
    __syncthreads();
  }
}

__device__ void ph_redye(float* dst, int bid, int nb, int tid) {
  int tot = (NB*DM) >> 2;  // 512 float4
  const float4* p4 = (const float4*)g_part;
  float4* d4 = (float4*)dst;
  for (int i = bid*256+tid; i < tot; i += nb*256) {
    float4 v = make_float4(0,0,0,0);
    #pragma unroll 16
    for (int t = 0; t < 128; t++) {
      float4 u = p4[(size_t)t*tot + i];
      v.x += u.x; v.y += u.y; v.z += u.z; v.w += u.w;
    }
    d4[i] = v;
  }
}

// ---------------- the megakernel ------------------------------------------
__global__ void __launch_bounds__(256) mega(P p, int nb) {
  __shared__ float sx[4*FF];     // 32 KB staging / gemm tiles
  __shared__ float sr[1024];     // 4 KB reduce scratch
  __shared__ unsigned sg;
  int tid = threadIdx.x, bid = blockIdx.x;
  if (tid == 0) sg = 0;
  __syncthreads();

  // ---------------- encoder ----------------
  ph_embed(p, bid, nb, tid);                                          gbar(nb,&sg);
  for (int l = 0; l < NL; l++) {
    size_t o2 = (size_t)l*DM*DM, of = (size_t)l*DM*FF;
    ph_rms(g_x, p.eln1 + (size_t)l*DM, g_h, NB*SS, sr, bid, nb, tid); gbar(nb,&sg);
    { const float* Ws[3] = { p.ewq+o2, p.ewk+o2, p.ewv+o2 };
      float* Cs[3] = { g_q, g_k, g_v };
      ph_gemm(g_h, Ws, Cs, 3, NB*SS, DM, DM, 0, 1, nullptr, sx, bid, nb, tid); }
    gbar(nb,&sg);
    ph_attn(g_q, g_k, g_v, g_att, SS, SS, (long long)SS*DM, (long long)DM,
            p.mask, NB*SS*NH, sr, bid, nb, tid);                      gbar(nb,&sg);
    { const float* Ws[1] = { p.ewo+o2 }; float* Cs[1] = { g_x };
      ph_gemm(g_att, Ws, Cs, 1, NB*SS, DM, DM, 2, 1, nullptr, sx, bid, nb, tid); }
    gbar(nb,&sg);
    ph_rms(g_x, p.eln2 + (size_t)l*DM, g_h, NB*SS, sr, bid, nb, tid); gbar(nb,&sg);
    { const float* Ws[1] = { p.ew1+of }; float* Cs[1] = { g_f };
      ph_gemm(g_h, Ws, Cs, 1, NB*SS, FF, DM, 1, 1, nullptr, sx, bid, nb, tid); }
    gbar(nb,&sg);
    { const float* Ws[1] = { p.ew2+of }; float* Cs[1] = { nullptr };
      ph_gemm(g_f, Ws, Cs, 1, NB*SS, DM, FF, 0, 4, g_gp, sx, bid, nb, tid); }
    gbar(nb,&sg);
    ph_gred(g_x, g_gp, NB*SS, DM, 4, 2, bid, nb, tid);                gbar(nb,&sg);
  }
  ph_rms(g_x, p.elnf, g_hs, NB*SS, sr, bid, nb, tid);                 gbar(nb,&sg);
  { const float* Ws[4] = { p.dck, p.dcv, p.dck + (size_t)DM*DM, p.dcv + (size_t)DM*DM };
    float* Cs[4] = { g_ck, g_cv, g_ck + (size_t)NB*SS*DM, g_cv + (size_t)NB*SS*DM };
    ph_gemm(g_hs, Ws, Cs, 4, NB*SS, DM, DM, 0, 1, nullptr, sx, bid, nb, tid); }
  gbar(nb,&sg);

  // ---------------- decoder: 16 incremental KV-cached steps ----------------
  for (int it = 0; it < NT; it++) {
    const float* xin = g_ye + (size_t)it*NB*DM;
    if (bid == nb-1)
      for (int e = tid; e < NB*DM; e += 256) g_xd[e] = xin[e];
    for (int l = 0; l < NL; l++) {
      size_t o2 = (size_t)l*DM*DM, of = (size_t)l*DM*FF;
      const float* lx = (l == 0) ? xin : g_xd;
      { const float* Ws[3] = { p.dsq+o2, p.dsk+o2, p.dsv+o2 };
        float* Os[3] = { g_qd,
                         g_sk + ((size_t)l*(NT+1) + it)*NB*DM,
                         g_sv + ((size_t)l*(NT+1) + it)*NB*DM };
        ph_gemv(lx, Ws, Os, 3, DM, DM, p.dln1 + (size_t)l*DM, 0, sx, sr, bid, nb, tid); }
      gbar(nb,&sg);
      ph_attn(g_qd, g_sk + (size_t)l*(NT+1)*NB*DM, g_sv + (size_t)l*(NT+1)*NB*DM,
              g_ad, 1, it+1, (long long)DM, (long long)NB*DM, nullptr,
              NB*NH, sr, bid, nb, tid);
      gbar(nb,&sg);
      { const float* Ws[1] = { p.dso+o2 }; float* Os[1] = { g_xd };
        ph_gemv(g_ad, Ws, Os, 1, DM, DM, nullptr, 2, sx, sr, bid, nb, tid); }
      gbar(nb,&sg);
      { const float* Ws[1] = { p.dcq+o2 }; float* Os[1] = { g_qd };
        ph_gemv(g_xd, Ws, Os, 1, DM, DM, p.dln2 + (size_t)l*DM, 0, sx, sr, bid, nb, tid); }
      gbar(nb,&sg);
      ph_attn(g_qd, g_ck + (size_t)l*NB*SS*DM, g_cv + (size_t)l*NB*SS*DM,
              g_ad, 1, SS, (long long)SS*DM, (long long)DM, p.mask,
              NB*NH, sr, bid, nb, tid);
      gbar(nb,&sg);
      { const float* Ws[1] = { p.dco+o2 }; float* Os[1] = { g_xd };
        ph_gemv(g_ad, Ws, Os, 1, DM, DM, nullptr, 2, sx, sr, bid, nb, tid); }
      gbar(nb,&sg);
      { const float* Ws[1] = { p.dw1+of }; float* Os[1] = { g_fd };
        ph_gemv(g_xd, Ws, Os, 1, FF, DM, p.dln3 + (size_t)l*DM, 1, sx, sr, bid, nb, tid); }
      gbar(nb,&sg);
      ph_gemv_ks(g_fd, p.dw2+of, DM, FF, 8, g_vp, sx, sr, bid, nb, tid);
      gbar(nb,&sg);
      ph_vred(g_xd, g_vp, 8, DM, 2, bid, nb, tid);
      gbar(nb,&sg);
    }
    { const float* Ws[1] = { p.lm }; float* Os[1] = { g_lg };
      ph_gemv(g_xd, Ws, Os, 1, NV, DM, p.dlnf, 0, sx, sr, bid, nb, tid); }
    gbar(nb,&sg);
    ph_sm1(sr, bid, nb, tid);
    gbar(nb,&sg);
    ph_sm2(p, it, bid, nb, tid);
    if (it < NT-1) {
      gbar(nb,&sg);
      ph_bp(p.out + (size_t)it*NV, p.emb, sx, bid, nb, tid);
      gbar(nb,&sg);
      ph_redye(g_ye + (size_t)(it+1)*NB*DM, bid, nb, tid);
    }
    gbar(nb,&sg);
  }
  // reset barrier counter for the next launch/replay (all blocks have arrived)
  if (bid == 0 && tid == 0) {
    unsigned z = 0;
    asm volatile("st.release.gpu.u32 [%0], %1;" :: "l"(&g_cnt), "r"(z) : "memory");
  }
}

// ---------------- host ------------------------------------------------------
extern "C" void kernel_launch(void* const* d_in, const int* in_sizes, int n_in,
                              void* d_out, int out_size) {
  P p;
  p.ids   = (const int*)  d_in[0];
  p.mask  = (const float*)d_in[1];
  p.emb   = (const float*)d_in[2];
  p.ewq   = (const float*)d_in[3];
  p.ewk   = (const float*)d_in[4];
  p.ewv   = (const float*)d_in[5];
  p.ewo   = (const float*)d_in[6];
  p.eln1  = (const float*)d_in[7];
  p.ew1   = (const float*)d_in[8];
  p.ew2   = (const float*)d_in[9];
  p.eln2  = (const float*)d_in[10];
  p.elnf  = (const float*)d_in[11];
  p.dsq   = (const float*)d_in[12];
  p.dsk   = (const float*)d_in[13];
  p.dsv   = (const float*)d_in[14];
  p.dso   = (const float*)d_in[15];
  p.dln1  = (const float*)d_in[16];
  p.dcq   = (const float*)d_in[17];
  p.dck   = (const float*)d_in[18];
  p.dcv   = (const float*)d_in[19];
  p.dco   = (const float*)d_in[20];
  p.dln2  = (const float*)d_in[21];
  p.dw1   = (const float*)d_in[22];
  p.dw2   = (const float*)d_in[23];
  p.dln3  = (const float*)d_in[24];
  p.dlnf  = (const float*)d_in[25];
  p.lm    = (const float*)d_in[26];
  p.out   = (float*)d_out;
  p.wp    = (out_size > NB*NT*NV) ? 1 : 0;

  int dev = 0; cudaGetDevice(&dev);
  int sms = 0; cudaDeviceGetAttribute(&sms, cudaDevAttrMultiProcessorCount, dev);
  mega<<<sms, 256>>>(p, sms);
}

// round 4
// speedup vs baseline: 9.5299x; 1.7120x over previous
#include <cuda_runtime.h>
#include <cuda_fp16.h>
#include <math.h>

#define NB 4
#define SS 64
#define DM 512
#define NH 8
#define DHD 64
#define FF 2048
#define NL 2
#define NV 32128
#define NT 16
#define NEGB (-1e9f)
#define BPT 240            // backproj tasks
#define BPC 134            // vocab rows per backproj task

// ---------------- device scratch (static, no allocs) ----------------------
static __device__ float g_x[NB*SS*DM];
static __device__ float g_h[NB*SS*DM];
static __device__ float g_q[NB*SS*DM];
static __device__ float g_k[NB*SS*DM];
static __device__ float g_v[NB*SS*DM];
static __device__ float g_att[NB*SS*DM];
static __device__ float g_f[NB*SS*FF];
static __device__ float g_hs[NB*SS*DM];
static __device__ float g_gp[4*NB*SS*DM];
static __device__ float g_ck[NL*NB*SS*DM];
static __device__ float g_cv[NL*NB*SS*DM];
static __device__ float g_sk[NL*(NT+1)*NB*DM];
static __device__ float g_sv[NL*(NT+1)*NB*DM];
static __device__ float g_ye[(NT+1)*NB*DM];
static __device__ float g_xd[NB*DM];
static __device__ float g_qd[NB*DM];
static __device__ float g_ad[NB*DM];
static __device__ float g_fd[NB*FF];
static __device__ float g_lg[NB*NV];
static __device__ float g_vp[4*4*DM];
static __device__ float g_part[BPT*NB*DM];
static __device__ float g_pm[NB*16], g_ps[NB*16];
static __device__ int   g_pi[NB*16];
static __device__ __align__(16) __half g_lmh[(size_t)DM*NV];   // [K][N] fp16
static __device__ __align__(16) __half g_embh[(size_t)NV*DM];  // [V][D] fp16
static __device__ unsigned g_cnt;

struct P {
  const int* ids; const float* mask; const float* emb;
  const float *ewq,*ewk,*ewv,*ewo,*eln1,*ew1,*ew2,*eln2,*elnf;
  const float *dsq,*dsk,*dsv,*dso,*dln1;
  const float *dcq,*dck,*dcv,*dco,*dln2;
  const float *dw1,*dw2,*dln3,*dlnf,*lm;
  float* out; int wp;
};

// ---------------- grid barrier ---------------------------------------------
__device__ __forceinline__ void gbar(int nb, unsigned* sgp) {
  __syncthreads();
  if (threadIdx.x == 0) {
    unsigned tgt = *sgp + (unsigned)nb;
    asm volatile("red.release.gpu.add.u32 [%0], 1;" :: "l"(&g_cnt) : "memory");
    unsigned v;
    do { asm volatile("ld.acquire.gpu.u32 %0, [%1];" : "=r"(v) : "l"(&g_cnt) : "memory"); }
    while ((int)(v - tgt) < 0);
    *sgp = tgt;
  }
  __syncthreads();
}

// ---------------- phases ----------------------------------------------------

__device__ void ph_conv(const float* lm, const float* emb, int bid, int nb, int tid) {
  size_t tot = (size_t)NV*DM/4;
  const float4* a4 = (const float4*)lm;
  const float4* e4 = (const float4*)emb;
  uint2* lo = (uint2*)g_lmh;
  uint2* eo = (uint2*)g_embh;
  for (size_t i = (size_t)bid*256 + tid; i < tot; i += (size_t)nb*256) {
    float4 v = a4[i];
    __half2 h0 = __floats2half2_rn(v.x, v.y), h1 = __floats2half2_rn(v.z, v.w);
    uint2 o; o.x = *(unsigned*)&h0; o.y = *(unsigned*)&h1;
    lo[i] = o;
    v = e4[i];
    h0 = __floats2half2_rn(v.x, v.y); h1 = __floats2half2_rn(v.z, v.w);
    o.x = *(unsigned*)&h0; o.y = *(unsigned*)&h1;
    eo[i] = o;
  }
}

__device__ void ph_embed(const P& p, int bid, int nb, int tid) {
  for (int r = bid; r < NB*SS; r += nb) {
    int id = p.ids[r];
    const float4* s = (const float4*)(p.emb + (size_t)id*DM);
    float4* d = (float4*)(g_x + (size_t)r*DM);
    for (int i = tid; i < DM/4; i += 256) d[i] = s[i];
  }
  if (bid == 0) {
    for (int i = tid; i < NB*DM; i += 256) g_ye[i] = p.emb[i & (DM-1)];
  }
}

__device__ void ph_rms(const float* x, const float* ln, float* o, int rows,
                       float* sr, int bid, int nb, int tid) {
  const float4* x4 = (const float4*)x;
  const float4* l4 = (const float4*)ln;
  float4* o4 = (float4*)o;
  for (int r = bid; r < rows; r += nb) {
    float s = 0.f;
    for (int i = tid; i < DM/4; i += 256) {
      float4 v = x4[(size_t)r*(DM/4)+i];
      s += v.x*v.x + v.y*v.y + v.z*v.z + v.w*v.w;
    }
    sr[tid] = s; __syncthreads();
    for (int st = 128; st; st >>= 1) { if (tid < st) sr[tid] += sr[tid+st]; __syncthreads(); }
    float sc = rsqrtf(sr[0]*(1.f/DM) + 1e-6f);
    __syncthreads();
    for (int i = tid; i < DM/4; i += 256) {
      float4 v = x4[(size_t)r*(DM/4)+i]; float4 lw = l4[i];
      v.x *= sc*lw.x; v.y *= sc*lw.y; v.z *= sc*lw.z; v.w *= sc*lw.w;
      o4[(size_t)r*(DM/4)+i] = v;
    }
  }
}

// encoder GEMM: 64x64 tile, 4x4 micro-tile, optional K-split to partials
__device__ void ph_gemm(const float* A, const float* const* Ws, float* const* Cs, int nW,
                        int M, int N, int K, int flags, int ksp, float* Cpart,
                        float* sx, int bid, int nb, int tid) {
  int mt = M >> 6, nt = N >> 6;
  int per = mt*nt*ksp;
  int ntasks = nW*per;
  if (bid >= ntasks) return;
  float* As = sx;
  float* Wt = sx + 1024;
  int Klen = K / ksp;
  int tr = tid >> 4, tc = tid & 15;
  int arow = tid >> 2, akq = tid & 3;
  int wkk = tid >> 4, wcc = (tid & 15) << 2;
  for (int t = bid; t < ntasks; t += nb) {
    int wi = t / per, r = t % per;
    int kc = r / (mt*nt); int r2 = r % (mt*nt);
    int m0 = (r2 / nt) << 6, n0 = (r2 % nt) << 6;
    int kb = kc*Klen;
    const float* W = Ws[wi];
    float acc[4][4];
    #pragma unroll
    for (int i = 0; i < 4; i++)
      #pragma unroll
      for (int j = 0; j < 4; j++) acc[i][j] = 0.f;
    for (int kt = 0; kt < Klen; kt += 16) {
      __syncthreads();
      float4 av = *(const float4*)&A[(size_t)(m0+arow)*K + kb + kt + (akq<<2)];
      As[(akq*4+0)*64 + arow] = av.x;
      As[(akq*4+1)*64 + arow] = av.y;
      As[(akq*4+2)*64 + arow] = av.z;
      As[(akq*4+3)*64 + arow] = av.w;
      *(float4*)&Wt[wkk*64 + wcc] = *(const float4*)&W[(size_t)(kb+kt+wkk)*N + n0 + wcc];
      __syncthreads();
      #pragma unroll
      for (int kk = 0; kk < 16; kk++) {
        float4 a = *(const float4*)&As[kk*64 + (tr<<2)];
        float4 w = *(const float4*)&Wt[kk*64 + (tc<<2)];
        acc[0][0]=fmaf(a.x,w.x,acc[0][0]); acc[0][1]=fmaf(a.x,w.y,acc[0][1]);
        acc[0][2]=fmaf(a.x,w.z,acc[0][2]); acc[0][3]=fmaf(a.x,w.w,acc[0][3]);
        acc[1][0]=fmaf(a.y,w.x,acc[1][0]); acc[1][1]=fmaf(a.y,w.y,acc[1][1]);
        acc[1][2]=fmaf(a.y,w.z,acc[1][2]); acc[1][3]=fmaf(a.y,w.w,acc[1][3]);
        acc[2][0]=fmaf(a.z,w.x,acc[2][0]); acc[2][1]=fmaf(a.z,w.y,acc[2][1]);
        acc[2][2]=fmaf(a.z,w.z,acc[2][2]); acc[2][3]=fmaf(a.z,w.w,acc[2][3]);
        acc[3][0]=fmaf(a.w,w.x,acc[3][0]); acc[3][1]=fmaf(a.w,w.y,acc[3][1]);
        acc[3][2]=fmaf(a.w,w.z,acc[3][2]); acc[3][3]=fmaf(a.w,w.w,acc[3][3]);
      }
    }
    #pragma unroll
    for (int i = 0; i < 4; i++) {
      float4 v = make_float4(acc[i][0], acc[i][1], acc[i][2], acc[i][3]);
      if (ksp == 1) {
        if (flags & 1) { v.x=fmaxf(v.x,0.f); v.y=fmaxf(v.y,0.f); v.z=fmaxf(v.z,0.f); v.w=fmaxf(v.w,0.f); }
        float4* cp = (float4*)&Cs[wi][(size_t)(m0+(tr<<2)+i)*N + n0 + (tc<<2)];
        if (flags & 2) { float4 o = *cp; o.x+=v.x; o.y+=v.y; o.z+=v.z; o.w+=v.w; *cp = o; }
        else *cp = v;
      } else {
        *(float4*)&Cpart[((size_t)kc*M + m0+(tr<<2)+i)*N + n0 + (tc<<2)] = v;
      }
    }
  }
}

__device__ void ph_gred(float* C, const float* part, int M, int N, int ksp, int flags,
                        int bid, int nb, int tid) {
  int tot = (M*N) >> 2;
  const float4* p4 = (const float4*)part;
  float4* c4 = (float4*)C;
  for (int i = bid*256+tid; i < tot; i += nb*256) {
    float4 v = p4[i];
    for (int kc = 1; kc < ksp; kc++) {
      float4 u = p4[(size_t)kc*tot + i];
      v.x += u.x; v.y += u.y; v.z += u.z; v.w += u.w;
    }
    if (flags & 1) { v.x=fmaxf(v.x,0.f); v.y=fmaxf(v.y,0.f); v.z=fmaxf(v.z,0.f); v.w=fmaxf(v.w,0.f); }
    if (flags & 2) { float4 o = c4[i]; o.x+=v.x; o.y+=v.y; o.z+=v.z; o.w+=v.w; c4[i] = o; }
    else c4[i] = v;
  }
}

// attention: warp per (query row, head). Tk <= 64.
__device__ void ph_attn(const float* q, const float* kc, const float* vc, float* o,
                        int Tq, int Tk, long long kbs, long long kts,
                        const float* mask, int ntasks,
                        float* sr, int bid, int nb, int tid) {
  int wid = tid >> 5, lane = tid & 31;
  float* ws = sr + wid*128;
  for (int t = bid*8 + wid; t < ntasks; t += nb*8) {
    int h = t & 7, rq = t >> 3, b = rq / Tq;
    const float* qp = q + (size_t)rq*DM + h*DHD;
    ws[lane] = qp[lane]; ws[32+lane] = qp[32+lane];
    __syncwarp();
    float s0 = -3e38f, s1 = -3e38f;
    if (lane < Tk) {
      const float* kp = kc + (size_t)b*kbs + (size_t)lane*kts + h*DHD;
      float d = 0.f;
      #pragma unroll 8
      for (int i = 0; i < DHD; i++) d = fmaf(ws[i], kp[i], d);
      s0 = d*0.125f;
      if (mask) s0 += (1.f - mask[b*SS + lane])*NEGB;
    }
    if (lane+32 < Tk) {
      const float* kp = kc + (size_t)b*kbs + (size_t)(lane+32)*kts + h*DHD;
      float d = 0.f;
      #pragma unroll 8
      for (int i = 0; i < DHD; i++) d = fmaf(ws[i], kp[i], d);
      s1 = d*0.125f;
      if (mask) s1 += (1.f - mask[b*SS + lane+32])*NEGB;
    }
    float m = fmaxf(s0, s1);
    #pragma unroll
    for (int off = 16; off; off >>= 1) m = fmaxf(m, __shfl_xor_sync(0xffffffffu, m, off));
    float e0 = (lane < Tk)    ? expf(s0 - m) : 0.f;
    float e1 = (lane+32 < Tk) ? expf(s1 - m) : 0.f;
    float su = e0 + e1;
    #pragma unroll
    for (int off = 16; off; off >>= 1) su += __shfl_xor_sync(0xffffffffu, su, off);
    __syncwarp();
    ws[64+lane] = e0; ws[96+lane] = e1;
    __syncwarp();
    float inv = 1.f/su;
    float o0 = 0.f, o1 = 0.f;
    const float* vb = vc + (size_t)b*kbs + h*DHD;
    for (int j = 0; j < Tk; j++) {
      float pj = ws[64+j];
      const float* vp = vb + (size_t)j*kts;
      o0 = fmaf(pj, vp[lane], o0);
      o1 = fmaf(pj, vp[32+lane], o1);
    }
    float* op = o + (size_t)rq*DM + h*DHD;
    op[lane] = o0*inv; op[32+lane] = o1*inv;
    __syncwarp();
  }
}

// decode GEMV: 16-col tiles, 64-way in-block K-split (+optional block K-split)
__device__ void ph_gemv(const float* x, const float* const* Ws, float* const* Os, int nW,
                        int N, int K, const float* ln, int flags, int bksp, float* part,
                        float* sx, float* sr, int bid, int nb, int tid) {
  int ntile = N >> 4;
  int per = ntile * bksp;
  int ntasks = nW * per;
  if (bid >= ntasks) return;
  int K4 = K >> 2;
  const float4* x4 = (const float4*)x;
  float4* sx4 = (float4*)sx;
  if (ln) {
    float s[4];
    #pragma unroll
    for (int m = 0; m < 4; m++) {
      float acc = 0.f;
      for (int i = tid; i < K4; i += 256) {
        float4 v = x4[m*K4+i]; sx4[m*K4+i] = v;
        acc += v.x*v.x + v.y*v.y + v.z*v.z + v.w*v.w;
      }
      s[m] = acc;
    }
    #pragma unroll
    for (int m = 0; m < 4; m++) sr[m*256+tid] = s[m];
    __syncthreads();
    for (int st = 128; st; st >>= 1) {
      if (tid < st)
        #pragma unroll
        for (int m = 0; m < 4; m++) sr[m*256+tid] += sr[m*256+tid+st];
      __syncthreads();
    }
    float sc[4];
    #pragma unroll
    for (int m = 0; m < 4; m++) sc[m] = rsqrtf(sr[m*256]*(1.f/K) + 1e-6f);
    __syncthreads();
    const float4* ln4 = (const float4*)ln;
    for (int i = tid; i < K4; i += 256) {
      float4 lw = ln4[i];
      #pragma unroll
      for (int m = 0; m < 4; m++) {
        float4 v = sx4[m*K4+i];
        v.x *= sc[m]*lw.x; v.y *= sc[m]*lw.y; v.z *= sc[m]*lw.z; v.w *= sc[m]*lw.w;
        sx4[m*K4+i] = v;
      }
    }
  } else {
    for (int i = tid; i < 4*K4; i += 256) sx4[i] = x4[i];
  }
  __syncthreads();
  int c = tid & 3, ksl = tid >> 2;
  int KS = K / (bksp << 6);
  int N4v = N >> 2;
  int w8 = tid >> 5;
  float4* sr4 = (float4*)sr;
  for (int t = bid; t < ntasks; t += nb) {
    int wi = t / per, r = t % per;
    int bk = r / ntile, tn = r % ntile;
    int kb = bk*(K/bksp) + ksl*KS;
    const float4* wp = (const float4*)Ws[wi] + (size_t)kb*N4v + tn*4 + c;
    float4 a[4];
    #pragma unroll
    for (int m = 0; m < 4; m++) a[m] = make_float4(0,0,0,0);
    #pragma unroll 8
    for (int kk = 0; kk < KS; kk++) {
      float4 w = wp[(size_t)kk*N4v];
      #pragma unroll
      for (int m = 0; m < 4; m++) {
        float xv = sx[m*K + kb + kk];
        a[m].x = fmaf(xv, w.x, a[m].x);
        a[m].y = fmaf(xv, w.y, a[m].y);
        a[m].z = fmaf(xv, w.z, a[m].z);
        a[m].w = fmaf(xv, w.w, a[m].w);
      }
    }
    #pragma unroll
    for (int off = 4; off <= 16; off <<= 1) {
      #pragma unroll
      for (int m = 0; m < 4; m++) {
        a[m].x += __shfl_xor_sync(0xffffffffu, a[m].x, off);
        a[m].y += __shfl_xor_sync(0xffffffffu, a[m].y, off);
        a[m].z += __shfl_xor_sync(0xffffffffu, a[m].z, off);
        a[m].w += __shfl_xor_sync(0xffffffffu, a[m].w, off);
      }
    }
    if ((ksl & 7) == 0) {
      #pragma unroll
      for (int m = 0; m < 4; m++) sr4[(w8*4 + c)*4 + m] = a[m];
    }
    __syncthreads();
    if (tid < 16) {
      int cc = tid & 3, m = tid >> 2;
      float4 v = sr4[cc*4 + m];
      #pragma unroll
      for (int w = 1; w < 8; w++) {
        float4 u = sr4[(w*4+cc)*4 + m];
        v.x += u.x; v.y += u.y; v.z += u.z; v.w += u.w;
      }
      if (bksp == 1) {
        if (flags & 1) { v.x=fmaxf(v.x,0.f); v.y=fmaxf(v.y,0.f); v.z=fmaxf(v.z,0.f); v.w=fmaxf(v.w,0.f); }
        float4* op = (float4*)(Os[wi] + (size_t)m*N) + tn*4 + cc;
        if (flags & 2) { float4 o = *op; o.x+=v.x; o.y+=v.y; o.z+=v.z; o.w+=v.w; *op = o; }
        else *op = v;
      } else {
        ((float4*)(part + ((size_t)(bk*4) + m)*N))[tn*4 + cc] = v;
      }
    }
    __syncthreads();
  }
}

__device__ void ph_vred(float* O, const float* part, int bksp, int N,
                        int bid, int nb, int tid) {
  const float4* p4 = (const float4*)part;
  float4* o4 = (float4*)O;
  int tot = N;  // 4*N/4 f4
  for (int i = bid*256+tid; i < tot; i += nb*256) {
    int m = i >> 7, j = i & 127;
    float4 v = p4[(size_t)m*(N>>2) + j];
    for (int bk = 1; bk < bksp; bk++) {
      float4 u = p4[((size_t)(bk*4)+m)*(N>>2) + j];
      v.x += u.x; v.y += u.y; v.z += u.z; v.w += u.w;
    }
    float4 o = o4[i]; o.x+=v.x; o.y+=v.y; o.z+=v.z; o.w+=v.w; o4[i] = o;
  }
}

// lm_head GEMV with fp16 weights, fused final RMSNorm
__device__ void ph_lmgemv(const float* x, const float* ln,
                          float* sx, float* sr, int bid, int nb, int tid) {
  // stage + rms (K=512)
  const float4* x4 = (const float4*)x;
  float4* sx4 = (float4*)sx;
  float s[4];
  #pragma unroll
  for (int m = 0; m < 4; m++) {
    float acc = 0.f;
    for (int i = tid; i < 128; i += 256) {
      float4 v = x4[m*128+i]; sx4[m*128+i] = v;
      acc += v.x*v.x + v.y*v.y + v.z*v.z + v.w*v.w;
    }
    s[m] = acc;
  }
  #pragma unroll
  for (int m = 0; m < 4; m++) sr[m*256+tid] = s[m];
  __syncthreads();
  for (int st = 128; st; st >>= 1) {
    if (tid < st)
      #pragma unroll
      for (int m = 0; m < 4; m++) sr[m*256+tid] += sr[m*256+tid+st];
    __syncthreads();
  }
  float sc[4];
  #pragma unroll
  for (int m = 0; m < 4; m++) sc[m] = rsqrtf(sr[m*256]*(1.f/DM) + 1e-6f);
  __syncthreads();
  const float4* ln4 = (const float4*)ln;
  for (int i = tid; i < 128; i += 256) {
    float4 lw = ln4[i];
    #pragma unroll
    for (int m = 0; m < 4; m++) {
      float4 v = sx4[m*128+i];
      v.x *= sc[m]*lw.x; v.y *= sc[m]*lw.y; v.z *= sc[m]*lw.z; v.w *= sc[m]*lw.w;
      sx4[m*128+i] = v;
    }
  }
  __syncthreads();
  int ntasks = NV/128;  // 251
  if (bid >= ntasks) return;
  int c = tid & 15, ks = tid >> 4;
  float* red = sx + 4*DM;   // 2048 floats at sx+2048
  for (int t = bid; t < ntasks; t += nb) {
    int n8 = t*128 + c*8;
    float a[4][8];
    #pragma unroll
    for (int m = 0; m < 4; m++)
      #pragma unroll
      for (int j = 0; j < 8; j++) a[m][j] = 0.f;
    const __half* wb = g_lmh + (size_t)(ks*32)*NV + n8;
    #pragma unroll 4
    for (int kk = 0; kk < 32; kk++) {
      uint4 raw = *(const uint4*)(wb + (size_t)kk*NV);
      float2 f0 = __half22float2(*(__half2*)&raw.x);
      float2 f1 = __half22float2(*(__half2*)&raw.y);
      float2 f2 = __half22float2(*(__half2*)&raw.z);
      float2 f3 = __half22float2(*(__half2*)&raw.w);
      #pragma unroll
      for (int m = 0; m < 4; m++) {
        float xv = sx[m*DM + ks*32 + kk];
        a[m][0] = fmaf(xv, f0.x, a[m][0]); a[m][1] = fmaf(xv, f0.y, a[m][1]);
        a[m][2] = fmaf(xv, f1.x, a[m][2]); a[m][3] = fmaf(xv, f1.y, a[m][3]);
        a[m][4] = fmaf(xv, f2.x, a[m][4]); a[m][5] = fmaf(xv, f2.y, a[m][5]);
        a[m][6] = fmaf(xv, f3.x, a[m][6]); a[m][7] = fmaf(xv, f3.y, a[m][7]);
      }
    }
    #pragma unroll
    for (int m = 0; m < 4; m++) {
      #pragma unroll
      for (int j = 0; j < 8; j++) red[ks*128 + c*8 + j] = a[m][j];
      __syncthreads();
      if (tid < 128) {
        float v = red[tid];
        #pragma unroll
        for (int k2 = 1; k2 < 16; k2++) v += red[k2*128 + tid];
        g_lg[(size_t)m*NV + t*128 + tid] = v;
      }
      __syncthreads();
    }
  }
}

// softmax phase 1: per (batch, chunk) partial max/argmax/sum-exp
__device__ void ph_sm1(float* sr, int bid, int nb, int tid) {
  const int CL = NV/16;
  int* si = (int*)(sr + 256);
  for (int t = bid; t < NB*16; t += nb) {
    int b = t >> 4, ch = t & 15;
    const float* lg = g_lg + (size_t)b*NV + ch*CL;
    float mx = -3e38f; int mi = 0;
    for (int i = tid; i < CL; i += 256) {
      float v = lg[i];
      if (v > mx) { mx = v; mi = i; }
    }
    sr[tid] = mx; si[tid] = mi;
    __syncthreads();
    for (int st = 128; st; st >>= 1) {
      if (tid < st) {
        float a = sr[tid], c2 = sr[tid+st];
        int ia = si[tid], ic = si[tid+st];
        if (c2 > a || (c2 == a && ic < ia)) { sr[tid] = c2; si[tid] = ic; }
      }
      __syncthreads();
    }
    float gm = sr[0]; int gi = si[0];
    __syncthreads();
    float s = 0.f;
    for (int i = tid; i < CL; i += 256) s += expf(lg[i] - gm);
    sr[tid] = s; __syncthreads();
    for (int st = 128; st; st >>= 1) { if (tid < st) sr[tid] += sr[tid+st]; __syncthreads(); }
    if (tid == 0) { g_pm[t] = gm; g_ps[t] = sr[0]; g_pi[t] = gi + ch*CL; }
    __syncthreads();
  }
}

// merged: write probs to out AND backproj partials from logits (fp16 emb)
__device__ void ph_sm2bp(const P& p, int it, int skipbp,
                         float* sx, float* sr, int bid, int nb, int tid) {
  if (tid < 4) {
    int b = tid;
    float M = -3e38f;
    #pragma unroll
    for (int i = 0; i < 16; i++) M = fmaxf(M, g_pm[b*16+i]);
    float S = 0.f; int gi = -1;
    #pragma unroll
    for (int i = 0; i < 16; i++) {
      float m = g_pm[b*16+i];
      S += g_ps[b*16+i]*expf(m - M);
      if (gi < 0 && m == M) gi = g_pi[b*16+i];
    }
    sr[512+b] = M; sr[516+b] = 1.f/S; ((int*)sr)[520+b] = gi;
  }
  __syncthreads();
  const int CL = NV/16;
  int ntasks = 64 + BPT;
  for (int t = bid; t < ntasks; t += nb) {
    if (t < 64) {
      int b = t >> 4, ch = t & 15;
      float M = sr[512+b], inv = sr[516+b];
      const float* lg = g_lg + (size_t)b*NV + ch*CL;
      float* pd = p.out + ((size_t)b*NT + it)*NV + ch*CL;
      for (int i = tid; i < CL; i += 256) pd[i] = expf(lg[i] - M)*inv;
      if (ch == 0 && tid == 0 && p.wp)
        p.out[(size_t)NB*NT*NV + (size_t)b*NT + it] = (((int*)sr)[520+b] == 0) ? 1.f : 0.f;
    } else if (!skipbp) {
      int tt = t - 64;
      int kb = tt*BPC;
      int klen = NV - kb; if (klen > BPC) klen = BPC;
      if (klen <= 0) continue;
      // stage probs chunk into smem
      for (int idx = tid; idx < 4*BPC; idx += 256) {
        int m = idx / BPC, k = idx - m*BPC;
        float v = 0.f;
        if (k < klen) v = expf(g_lg[(size_t)m*NV + kb + k] - sr[512+m]) * sr[516+m];
        sx[m*BPC + k] = v;
      }
      __syncthreads();
      int c = tid & 127, ks = tid >> 7;
      int k0 = ks*67, k1 = k0 + 67; if (k1 > klen) k1 = klen; if (k0 > klen) k0 = klen;
      float4 a[4];
      #pragma unroll
      for (int m = 0; m < 4; m++) a[m] = make_float4(0,0,0,0);
      #pragma unroll 4
      for (int k = k0; k < k1; k++) {
        uint2 raw = *(const uint2*)(g_embh + (size_t)(kb+k)*DM + c*4);
        float2 e0 = __half22float2(*(__half2*)&raw.x);
        float2 e1 = __half22float2(*(__half2*)&raw.y);
        #pragma unroll
        for (int m = 0; m < 4; m++) {
          float pm = sx[m*BPC + k];
          a[m].x = fmaf(pm, e0.x, a[m].x);
          a[m].y = fmaf(pm, e0.y, a[m].y);
          a[m].z = fmaf(pm, e1.x, a[m].z);
          a[m].w = fmaf(pm, e1.y, a[m].w);
        }
      }
      float4* xr4 = (float4*)(sx + 1024);
      if (ks == 1) {
        #pragma unroll
        for (int m = 0; m < 4; m++) xr4[c*4+m] = a[m];
      }
      __syncthreads();
      if (ks == 0) {
        #pragma unroll
        for (int m = 0; m < 4; m++) {
          float4 u = xr4[c*4+m];
          a[m].x += u.x; a[m].y += u.y; a[m].z += u.z; a[m].w += u.w;
          ((float4*)g_part)[(size_t)tt*512 + m*128 + c] = a[m];
        }
      }
      __syncthreads();
    }
  }
}

// reduce 240 backproj partials -> ye[t+1]; one warp per float4 output
__device__ void ph_redye(float* dst, int bid, int nb, int tid) {
  int gw = bid*8 + (tid >> 5), lane = tid & 31;
  if (gw >= 512) return;
  const float4* p4 = (const float4*)g_part;
  float4 v = make_float4(0,0,0,0);
  for (int t = lane; t < BPT; t += 32) {
    float4 u = p4[(size_t)t*512 + gw];
    v.x += u.x; v.y += u.y; v.z += u.z; v.w += u.w;
  }
  #pragma unroll
  for (int off = 16; off; off >>= 1) {
    v.x += __shfl_xor_sync(0xffffffffu, v.x, off);
    v.y += __shfl_xor_sync(0xffffffffu, v.y, off);
    v.z += __shfl_xor_sync(0xffffffffu, v.z, off);
    v.w += __shfl_xor_sync(0xffffffffu, v.w, off);
  }
  if (lane == 0) ((float4*)dst)[gw] = v;
}

// ---------------- the megakernel ------------------------------------------
__global__ void __launch_bounds__(256, 2) mega(P p, int nb) {
  __shared__ float sx[4*FF];     // 32 KB
  __shared__ float sr[1024];     // 4 KB
  __shared__ unsigned sg;
  int tid = threadIdx.x, bid = blockIdx.x;
  if (tid == 0) sg = 0;
  __syncthreads();

  // startup: fp16 conversion + embedding (independent work, one phase)
  ph_conv(p.lm, p.emb, bid, nb, tid);
  ph_embed(p, bid, nb, tid);                                          gbar(nb,&sg);

  // ---------------- encoder ----------------
  for (int l = 0; l < NL; l++) {
    size_t o2 = (size_t)l*DM*DM, of = (size_t)l*DM*FF;
    ph_rms(g_x, p.eln1 + (size_t)l*DM, g_h, NB*SS, sr, bid, nb, tid); gbar(nb,&sg);
    { const float* Ws[3] = { p.ewq+o2, p.ewk+o2, p.ewv+o2 };
      float* Cs[3] = { g_q, g_k, g_v };
      ph_gemm(g_h, Ws, Cs, 3, NB*SS, DM, DM, 0, 1, nullptr, sx, bid, nb, tid); }
    gbar(nb,&sg);
    ph_attn(g_q, g_k, g_v, g_att, SS, SS, (long long)SS*DM, (long long)DM,
            p.mask, NB*SS*NH, sr, bid, nb, tid);                      gbar(nb,&sg);
    { const float* Ws[1] = { p.ewo+o2 }; float* Cs[1] = { g_x };
      ph_gemm(g_att, Ws, Cs, 1, NB*SS, DM, DM, 2, 1, nullptr, sx, bid, nb, tid); }
    gbar(nb,&sg);
    ph_rms(g_x, p.eln2 + (size_t)l*DM, g_h, NB*SS, sr, bid, nb, tid); gbar(nb,&sg);
    { const float* Ws[1] = { p.ew1+of }; float* Cs[1] = { g_f };
      ph_gemm(g_h, Ws, Cs, 1, NB*SS, FF, DM, 1, 1, nullptr, sx, bid, nb, tid); }
    gbar(nb,&sg);
    { const float* Ws[1] = { p.ew2+of }; float* Cs[1] = { nullptr };
      ph_gemm(g_f, Ws, Cs, 1, NB*SS, DM, FF, 0, 4, g_gp, sx, bid, nb, tid); }
    gbar(nb,&sg);
    ph_gred(g_x, g_gp, NB*SS, DM, 4, 2, bid, nb, tid);                gbar(nb,&sg);
  }
  ph_rms(g_x, p.elnf, g_hs, NB*SS, sr, bid, nb, tid);                 gbar(nb,&sg);
  { const float* Ws[4] = { p.dck, p.dcv, p.dck + (size_t)DM*DM, p.dcv + (size_t)DM*DM };
    float* Cs[4] = { g_ck, g_cv, g_ck + (size_t)NB*SS*DM, g_cv + (size_t)NB*SS*DM };
    ph_gemm(g_hs, Ws, Cs, 4, NB*SS, DM, DM, 0, 1, nullptr, sx, bid, nb, tid); }
  gbar(nb,&sg);

  // ---------------- decoder ----------------
  for (int it = 0; it < NT; it++) {
    const float* xin = g_ye + (size_t)it*NB*DM;
    if (bid == nb-1)
      for (int e = tid; e < NB*DM; e += 256) g_xd[e] = xin[e];
    for (int l = 0; l < NL; l++) {
      size_t o2 = (size_t)l*DM*DM, of = (size_t)l*DM*FF;
      const float* lx = (l == 0) ? xin : g_xd;
      { const float* Ws[3] = { p.dsq+o2, p.dsk+o2, p.dsv+o2 };
        float* Os[3] = { g_qd,
                         g_sk + ((size_t)l*(NT+1) + it)*NB*DM,
                         g_sv + ((size_t)l*(NT+1) + it)*NB*DM };
        ph_gemv(lx, Ws, Os, 3, DM, DM, p.dln1 + (size_t)l*DM, 0, 1, nullptr, sx, sr, bid, nb, tid); }
      gbar(nb,&sg);
      ph_attn(g_qd, g_sk + (size_t)l*(NT+1)*NB*DM, g_sv + (size_t)l*(NT+1)*NB*DM,
              g_ad, 1, it+1, (long long)DM, (long long)NB*DM, nullptr,
              NB*NH, sr, bid, nb, tid);
      gbar(nb,&sg);
      { const float* Ws[1] = { p.dso+o2 }; float* Os[1] = { g_xd };
        ph_gemv(g_ad, Ws, Os, 1, DM, DM, nullptr, 2, 1, nullptr, sx, sr, bid, nb, tid); }
      gbar(nb,&sg);
      { const float* Ws[1] = { p.dcq+o2 }; float* Os[1] = { g_qd };
        ph_gemv(g_xd, Ws, Os, 1, DM, DM, p.dln2 + (size_t)l*DM, 0, 1, nullptr, sx, sr, bid, nb, tid); }
      gbar(nb,&sg);
      ph_attn(g_qd, g_ck + (size_t)l*NB*SS*DM, g_cv + (size_t)l*NB*SS*DM,
              g_ad, 1, SS, (long long)SS*DM, (long long)DM, p.mask,
              NB*NH, sr, bid, nb, tid);
      gbar(nb,&sg);
      { const float* Ws[1] = { p.dco+o2 }; float* Os[1] = { g_xd };
        ph_gemv(g_ad, Ws, Os, 1, DM, DM, nullptr, 2, 1, nullptr, sx, sr, bid, nb, tid); }
      gbar(nb,&sg);
      { const float* Ws[1] = { p.dw1+of }; float* Os[1] = { g_fd };
        ph_gemv(g_xd, Ws, Os, 1, FF, DM, p.dln3 + (size_t)l*DM, 1, 1, nullptr, sx, sr, bid, nb, tid); }
      gbar(nb,&sg);
      { const float* Ws[1] = { p.dw2+of }; float* Os[1] = { nullptr };
        ph_gemv(g_fd, Ws, Os, 1, DM, FF, nullptr, 0, 4, g_vp, sx, sr, bid, nb, tid); }
      gbar(nb,&sg);
      ph_vred(g_xd, g_vp, 4, DM, bid, nb, tid);
      gbar(nb,&sg);
    }
    ph_lmgemv(g_xd, p.dlnf, sx, sr, bid, nb, tid);
    gbar(nb,&sg);
    ph_sm1(sr, bid, nb, tid);
    gbar(nb,&sg);
    ph_sm2bp(p, it, it == NT-1, sx, sr, bid, nb, tid);
    if (it < NT-1) {
      gbar(nb,&sg);
      ph_redye(g_ye + (size_t)(it+1)*NB*DM, bid, nb, tid);
    }
    gbar(nb,&sg);
  }
  if (bid == 0 && tid == 0) {
    unsigned z = 0;
    asm volatile("st.release.gpu.u32 [%0], %1;" :: "l"(&g_cnt), "r"(z) : "memory");
  }
}

// ---------------- host ------------------------------------------------------
extern "C" void kernel_launch(void* const* d_in, const int* in_sizes, int n_in,
                              void* d_out, int out_size) {
  P p;
  p.ids   = (const int*)  d_in[0];
  p.mask  = (const float*)d_in[1];
  p.emb   = (const float*)d_in[2];
  p.ewq   = (const float*)d_in[3];
  p.ewk   = (const float*)d_in[4];
  p.ewv   = (const float*)d_in[5];
  p.ewo   = (const float*)d_in[6];
  p.eln1  = (const float*)d_in[7];
  p.ew1   = (const float*)d_in[8];
  p.ew2   = (const float*)d_in[9];
  p.eln2  = (const float*)d_in[10];
  p.elnf  = (const float*)d_in[11];
  p.dsq   = (const float*)d_in[12];
  p.dsk   = (const float*)d_in[13];
  p.dsv   = (const float*)d_in[14];
  p.dso   = (const float*)d_in[15];
  p.dln1  = (const float*)d_in[16];
  p.dcq   = (const float*)d_in[17];
  p.dck   = (const float*)d_in[18];
  p.dcv   = (const float*)d_in[19];
  p.dco   = (const float*)d_in[20];
  p.dln2  = (const float*)d_in[21];
  p.dw1   = (const float*)d_in[22];
  p.dw2   = (const float*)d_in[23];
  p.dln3  = (const float*)d_in[24];
  p.dlnf  = (const float*)d_in[25];
  p.lm    = (const float*)d_in[26];
  p.out   = (float*)d_out;
  p.wp    = (out_size > NB*NT*NV) ? 1 : 0;

  int dev = 0; cudaGetDevice(&dev);
  int sms = 0; cudaDeviceGetAttribute(&sms, cudaDevAttrMultiProcessorCount, dev);
  int nb = 2*sms;   // 2 resident blocks per SM (guaranteed by __launch_bounds__(256,2))
  mega<<<nb, 256>>>(p, nb);
}

// round 8
// speedup vs baseline: 10.0882x; 1.0586x over previous
#include <cuda_runtime.h>
#include <cuda_fp16.h>
#include <math.h>

#define NB 4
#define SS 64
#define DM 512
#define NH 8
#define DHD 64
#define FF 2048
#define NL 2
#define NV 32128
#define NT 16
#define NEGB (-1e9f)
#define BPT 240
#define BPC 134

// ---------------- device scratch (static, no allocs) ----------------------
static __device__ float g_x[NB*SS*DM];
static __device__ float g_h[NB*SS*DM];
static __device__ float g_q[NB*SS*DM];
static __device__ float g_k[NB*SS*DM];
static __device__ float g_v[NB*SS*DM];
static __device__ float g_att[NB*SS*DM];
static __device__ float g_f[NB*SS*FF];
static __device__ float g_hs[NB*SS*DM];
static __device__ float g_gp[4*NB*SS*DM];
static __device__ float g_ck[NL*NB*SS*DM];
static __device__ float g_cv[NL*NB*SS*DM];
static __device__ float g_sk[NL*(NT+1)*NB*DM];
static __device__ float g_sv[NL*(NT+1)*NB*DM];
static __device__ float g_ye[(NT+1)*NB*DM];
static __device__ float g_xd[NB*DM];
static __device__ float g_xd2[NB*DM];          // ping-pong residual (race fix)
static __device__ float g_qd[NB*DM];
static __device__ float g_ad[NB*DM];
static __device__ float g_fd[NB*FF];
static __device__ float g_lg[NB*NV];
static __device__ float g_vp[4*4*DM];          // w2 block-ksplit partials
static __device__ float g_part[BPT*NB*DM];
static __device__ float g_pm[NB*16], g_ps[NB*16];
static __device__ int   g_pi[NB*16];
static __device__ __align__(16) __half g_lmh[(size_t)DM*NV];    // [K][N]
static __device__ __align__(16) __half g_embh[(size_t)NV*DM];   // [V][D]
static __device__ unsigned g_cnt;

struct P {
  const int* ids; const float* mask; const float* emb;
  const float *ewq,*ewk,*ewv,*ewo,*eln1,*ew1,*ew2,*eln2,*elnf;
  const float *dsq,*dsk,*dsv,*dso,*dln1;
  const float *dcq,*dck,*dcv,*dco,*dln2;
  const float *dw1,*dw2,*dln3,*dlnf,*lm;
  float* out; int wp;
};

// ---------------- grid barrier ---------------------------------------------
__device__ __forceinline__ void gbar(int nb, unsigned* sgp) {
  __syncthreads();
  if (threadIdx.x == 0) {
    unsigned tgt = *sgp + (unsigned)nb;
    asm volatile("red.release.gpu.add.u32 [%0], 1;" :: "l"(&g_cnt) : "memory");
    unsigned v;
    do { asm volatile("ld.acquire.gpu.u32 %0, [%1];" : "=r"(v) : "l"(&g_cnt) : "memory"); }
    while ((int)(v - tgt) < 0);
    *sgp = tgt;
  }
  __syncthreads();
}

// ---------------- fp32 -> fp16 conversion ----------------------------------
__device__ void conv1(const float* s, __half* d, size_t n4, int bid, int nb, int tid) {
  const float4* s4 = (const float4*)s;
  uint2* d2 = (uint2*)d;
  for (size_t i = (size_t)bid*256 + tid; i < n4; i += (size_t)nb*256) {
    float4 v = s4[i];
    __half2 h0 = __floats2half2_rn(v.x, v.y), h1 = __floats2half2_rn(v.z, v.w);
    uint2 o; o.x = *(unsigned*)&h0; o.y = *(unsigned*)&h1;
    d2[i] = o;
  }
}

// ---------------- phases ----------------------------------------------------

__device__ void ph_embed(const P& p, int bid, int nb, int tid) {
  for (int r = bid; r < NB*SS; r += nb) {
    int id = p.ids[r];
    const float4* s = (const float4*)(p.emb + (size_t)id*DM);
    float4* d = (float4*)(g_x + (size_t)r*DM);
    for (int i = tid; i < DM/4; i += 256) d[i] = s[i];
  }
  if (bid == 0) {
    for (int i = tid; i < NB*DM; i += 256) g_ye[i] = p.emb[i & (DM-1)];
  }
}

__device__ void ph_rms(const float* x, const float* ln, float* o, int rows,
                       float* sr, int bid, int nb, int tid) {
  const float4* x4 = (const float4*)x;
  const float4* l4 = (const float4*)ln;
  float4* o4 = (float4*)o;
  for (int r = bid; r < rows; r += nb) {
    float s = 0.f;
    for (int i = tid; i < DM/4; i += 256) {
      float4 v = x4[(size_t)r*(DM/4)+i];
      s += v.x*v.x + v.y*v.y + v.z*v.z + v.w*v.w;
    }
    sr[tid] = s; __syncthreads();
    for (int st = 128; st; st >>= 1) { if (tid < st) sr[tid] += sr[tid+st]; __syncthreads(); }
    float sc = rsqrtf(sr[0]*(1.f/DM) + 1e-6f);
    __syncthreads();
    for (int i = tid; i < DM/4; i += 256) {
      float4 v = x4[(size_t)r*(DM/4)+i]; float4 lw = l4[i];
      v.x *= sc*lw.x; v.y *= sc*lw.y; v.z *= sc*lw.z; v.w *= sc*lw.w;
      o4[(size_t)r*(DM/4)+i] = v;
    }
  }
}

// encoder GEMM: 64x64 tile, 4x4 micro-tile, optional K-split to partials
__device__ void ph_gemm(const float* A, const float* const* Ws, float* const* Cs, int nW,
                        int M, int N, int K, int flags, int ksp, float* Cpart,
                        float* sx, int bid, int nb, int tid) {
  int mt = M >> 6, nt = N >> 6;
  int per = mt*nt*ksp;
  int ntasks = nW*per;
  if (bid >= ntasks) return;
  float* As = sx;
  float* Wt = sx + 1024;
  int Klen = K / ksp;
  int tr = tid >> 4, tc = tid & 15;
  int arow = tid >> 2, akq = tid & 3;
  int wkk = tid >> 4, wcc = (tid & 15) << 2;
  for (int t = bid; t < ntasks; t += nb) {
    int wi = t / per, r = t % per;
    int kc = r / (mt*nt); int r2 = r % (mt*nt);
    int m0 = (r2 / nt) << 6, n0 = (r2 % nt) << 6;
    int kb = kc*Klen;
    const float* W = Ws[wi];
    float acc[4][4];
    #pragma unroll
    for (int i = 0; i < 4; i++)
      #pragma unroll
      for (int j = 0; j < 4; j++) acc[i][j] = 0.f;
    for (int kt = 0; kt < Klen; kt += 16) {
      __syncthreads();
      float4 av = *(const float4*)&A[(size_t)(m0+arow)*K + kb + kt + (akq<<2)];
      As[(akq*4+0)*64 + arow] = av.x;
      As[(akq*4+1)*64 + arow] = av.y;
      As[(akq*4+2)*64 + arow] = av.z;
      As[(akq*4+3)*64 + arow] = av.w;
      *(float4*)&Wt[wkk*64 + wcc] = *(const float4*)&W[(size_t)(kb+kt+wkk)*N + n0 + wcc];
      __syncthreads();
      #pragma unroll
      for (int kk = 0; kk < 16; kk++) {
        float4 a = *(const float4*)&As[kk*64 + (tr<<2)];
        float4 w = *(const float4*)&Wt[kk*64 + (tc<<2)];
        acc[0][0]=fmaf(a.x,w.x,acc[0][0]); acc[0][1]=fmaf(a.x,w.y,acc[0][1]);
        acc[0][2]=fmaf(a.x,w.z,acc[0][2]); acc[0][3]=fmaf(a.x,w.w,acc[0][3]);
        acc[1][0]=fmaf(a.y,w.x,acc[1][0]); acc[1][1]=fmaf(a.y,w.y,acc[1][1]);
        acc[1][2]=fmaf(a.y,w.z,acc[1][2]); acc[1][3]=fmaf(a.y,w.w,acc[1][3]);
        acc[2][0]=fmaf(a.z,w.x,acc[2][0]); acc[2][1]=fmaf(a.z,w.y,acc[2][1]);
        acc[2][2]=fmaf(a.z,w.z,acc[2][2]); acc[2][3]=fmaf(a.z,w.w,acc[2][3]);
        acc[3][0]=fmaf(a.w,w.x,acc[3][0]); acc[3][1]=fmaf(a.w,w.y,acc[3][1]);
        acc[3][2]=fmaf(a.w,w.z,acc[3][2]); acc[3][3]=fmaf(a.w,w.w,acc[3][3]);
      }
    }
    #pragma unroll
    for (int i = 0; i < 4; i++) {
      float4 v = make_float4(acc[i][0], acc[i][1], acc[i][2], acc[i][3]);
      if (ksp == 1) {
        if (flags & 1) { v.x=fmaxf(v.x,0.f); v.y=fmaxf(v.y,0.f); v.z=fmaxf(v.z,0.f); v.w=fmaxf(v.w,0.f); }
        float4* cp = (float4*)&Cs[wi][(size_t)(m0+(tr<<2)+i)*N + n0 + (tc<<2)];
        if (flags & 2) { float4 o = *cp; o.x+=v.x; o.y+=v.y; o.z+=v.z; o.w+=v.w; *cp = o; }
        else *cp = v;
      } else {
        *(float4*)&Cpart[((size_t)kc*M + m0+(tr<<2)+i)*N + n0 + (tc<<2)] = v;
      }
    }
  }
}

__device__ void ph_gred(float* C, const float* part, int M, int N, int ksp, int flags,
                        int bid, int nb, int tid) {
  int tot = (M*N) >> 2;
  const float4* p4 = (const float4*)part;
  float4* c4 = (float4*)C;
  for (int i = bid*256+tid; i < tot; i += nb*256) {
    float4 v = p4[i];
    for (int kc = 1; kc < ksp; kc++) {
      float4 u = p4[(size_t)kc*tot + i];
      v.x += u.x; v.y += u.y; v.z += u.z; v.w += u.w;
    }
    if (flags & 1) { v.x=fmaxf(v.x,0.f); v.y=fmaxf(v.y,0.f); v.z=fmaxf(v.z,0.f); v.w=fmaxf(v.w,0.f); }
    if (flags & 2) { float4 o = c4[i]; o.x+=v.x; o.y+=v.y; o.z+=v.z; o.w+=v.w; c4[i] = o; }
    else c4[i] = v;
  }
}

// attention: warp per (query row, head). Tk <= 64.
__device__ void ph_attn(const float* q, const float* kc, const float* vc, float* o,
                        int Tq, int Tk, long long kbs, long long kts,
                        const float* mask, int ntasks,
                        float* sr, int bid, int nb, int tid) {
  int wid = tid >> 5, lane = tid & 31;
  float* ws = sr + wid*128;
  for (int t = bid*8 + wid; t < ntasks; t += nb*8) {
    int h = t & 7, rq = t >> 3, b = rq / Tq;
    const float* qp = q + (size_t)rq*DM + h*DHD;
    ws[lane] = qp[lane]; ws[32+lane] = qp[32+lane];
    __syncwarp();
    float s0 = -3e38f, s1 = -3e38f;
    if (lane < Tk) {
      const float* kp = kc + (size_t)b*kbs + (size_t)lane*kts + h*DHD;
      float d = 0.f;
      #pragma unroll 8
      for (int i = 0; i < DHD; i++) d = fmaf(ws[i], kp[i], d);
      s0 = d*0.125f;
      if (mask) s0 += (1.f - mask[b*SS + lane])*NEGB;
    }
    if (lane+32 < Tk) {
      const float* kp = kc + (size_t)b*kbs + (size_t)(lane+32)*kts + h*DHD;
      float d = 0.f;
      #pragma unroll 8
      for (int i = 0; i < DHD; i++) d = fmaf(ws[i], kp[i], d);
      s1 = d*0.125f;
      if (mask) s1 += (1.f - mask[b*SS + lane+32])*NEGB;
    }
    float m = fmaxf(s0, s1);
    #pragma unroll
    for (int off = 16; off; off >>= 1) m = fmaxf(m, __shfl_xor_sync(0xffffffffu, m, off));
    float e0 = (lane < Tk)    ? expf(s0 - m) : 0.f;
    float e1 = (lane+32 < Tk) ? expf(s1 - m) : 0.f;
    float su = e0 + e1;
    #pragma unroll
    for (int off = 16; off; off >>= 1) su += __shfl_xor_sync(0xffffffffu, su, off);
    __syncwarp();
    ws[64+lane] = e0; ws[96+lane] = e1;
    __syncwarp();
    float inv = 1.f/su;
    float o0 = 0.f, o1 = 0.f;
    const float* vb = vc + (size_t)b*kbs + h*DHD;
    for (int j = 0; j < Tk; j++) {
      float pj = ws[64+j];
      const float* vp = vb + (size_t)j*kts;
      o0 = fmaf(pj, vp[lane], o0);
      o1 = fmaf(pj, vp[32+lane], o1);
    }
    float* op = o + (size_t)rq*DM + h*DHD;
    op[lane] = o0*inv; op[32+lane] = o1*inv;
    __syncwarp();
  }
}

// stage x[4][512] into sx (fp32), with optional vp partial-fold, optional rms(ln),
// optional write-back of x_eff to xwb (xwb MUST differ from x — race-free ping-pong).
__device__ void stage512(const float* x, const float* vp, const float* ln, float* xwb,
                         float* sx, float* sr, int tid) {
  const float4* x4 = (const float4*)x;
  float4* sx4 = (float4*)sx;
  float4 va[2];
  float ss0 = 0.f, ss1 = 0.f;
  #pragma unroll
  for (int pp = 0; pp < 2; pp++) {
    int i = tid + pp*256;
    float4 v = x4[i];
    if (vp) {
      int m = i >> 7, d = i & 127;
      #pragma unroll
      for (int bk = 0; bk < 4; bk++) {
        float4 u = ((const float4*)vp)[(bk*4+m)*128 + d];
        v.x += u.x; v.y += u.y; v.z += u.z; v.w += u.w;
      }
    }
    if (xwb) ((float4*)xwb)[i] = v;
    va[pp] = v;
    float s = v.x*v.x + v.y*v.y + v.z*v.z + v.w*v.w;
    if (pp == 0) ss0 = s; else ss1 = s;
  }
  if (ln) {
    #pragma unroll
    for (int off = 16; off; off >>= 1) {
      ss0 += __shfl_xor_sync(0xffffffffu, ss0, off);
      ss1 += __shfl_xor_sync(0xffffffffu, ss1, off);
    }
    int wid = tid >> 5, lane = tid & 31;
    if (lane == 0) { sr[wid] = ss0; sr[8+wid] = ss1; }
    __syncthreads();
    const float4* ln4 = (const float4*)ln;
    #pragma unroll
    for (int pp = 0; pp < 2; pp++) {
      int i = tid + pp*256;
      int m = i >> 7, d = i & 127;
      float sum = sr[m*4] + sr[m*4+1] + sr[m*4+2] + sr[m*4+3];
      float sc = rsqrtf(sum*(1.f/DM) + 1e-6f);
      float4 lw = ln4[d];
      float4 v = va[pp];
      v.x *= sc*lw.x; v.y *= sc*lw.y; v.z *= sc*lw.z; v.w *= sc*lw.w;
      sx4[i] = v;
    }
  } else {
    sx4[tid] = va[0]; sx4[tid+256] = va[1];
  }
  __syncthreads();
}

// decode GEMV (fp32 weights): 16-col tiles, 64-way in-block K-split,
// optional block K-split to partials, optional vp-fold + xwb on staging.
__device__ void ph_gemv(const float* x, const float* vp, float* xwb,
                        const float* const* Ws, float* const* Os, int nW,
                        int N, int K, const float* ln, int flags, int bksp, float* part,
                        float* sx, float* sr, int bid, int nb, int tid) {
  int ntile = N >> 4;
  int per = ntile * bksp;
  int ntasks = nW * per;
  if (bid >= ntasks) return;
  if (K == 512) {
    stage512(x, vp, ln, (bid == 0) ? xwb : nullptr, sx, sr, tid);
  } else {
    const float4* x4 = (const float4*)x;
    float4* sx4 = (float4*)sx;
    for (int i = tid; i < (K >> 2); i += 256) {
      #pragma unroll
      for (int m = 0; m < 4; m++) sx4[m*(K>>2)+i] = x4[m*(K>>2)+i];
    }
    __syncthreads();
  }
  int c = tid & 3, ksl = tid >> 2;
  int KS = K / (bksp << 6);
  int N4 = N >> 2, w8 = tid >> 5;
  float4* sr4 = (float4*)sr;
  for (int t = bid; t < ntasks; t += nb) {
    int wi = t / per, r = t % per;
    int bk = r / ntile, tn = r % ntile;
    int kb = bk*(K/bksp) + ksl*KS;
    const float4* wp = (const float4*)Ws[wi] + (size_t)kb*N4 + tn*4 + c;
    float4 a[4];
    #pragma unroll
    for (int m = 0; m < 4; m++) a[m] = make_float4(0,0,0,0);
    #pragma unroll 8
    for (int kk = 0; kk < KS; kk++) {
      float4 w = wp[(size_t)kk*N4];
      #pragma unroll
      for (int m = 0; m < 4; m++) {
        float xv = sx[m*K + kb + kk];
        a[m].x = fmaf(xv, w.x, a[m].x);
        a[m].y = fmaf(xv, w.y, a[m].y);
        a[m].z = fmaf(xv, w.z, a[m].z);
        a[m].w = fmaf(xv, w.w, a[m].w);
      }
    }
    #pragma unroll
    for (int off = 4; off <= 16; off <<= 1) {
      #pragma unroll
      for (int m = 0; m < 4; m++) {
        a[m].x += __shfl_xor_sync(0xffffffffu, a[m].x, off);
        a[m].y += __shfl_xor_sync(0xffffffffu, a[m].y, off);
        a[m].z += __shfl_xor_sync(0xffffffffu, a[m].z, off);
        a[m].w += __shfl_xor_sync(0xffffffffu, a[m].w, off);
      }
    }
    if ((ksl & 7) == 0) {
      #pragma unroll
      for (int m = 0; m < 4; m++) sr4[(w8*4 + c)*4 + m] = a[m];
    }
    __syncthreads();
    if (tid < 16) {
      int cc = tid & 3, m = tid >> 2;
      float4 v = sr4[cc*4 + m];
      #pragma unroll
      for (int w = 1; w < 8; w++) {
        float4 u = sr4[(w*4+cc)*4 + m];
        v.x += u.x; v.y += u.y; v.z += u.z; v.w += u.w;
      }
      if (bksp == 1) {
        if (flags & 1) { v.x=fmaxf(v.x,0.f); v.y=fmaxf(v.y,0.f); v.z=fmaxf(v.z,0.f); v.w=fmaxf(v.w,0.f); }
        float4* op = (float4*)(Os[wi] + (size_t)m*N) + tn*4 + cc;
        if (flags & 2) { float4 o = *op; o.x+=v.x; o.y+=v.y; o.z+=v.z; o.w+=v.w; *op = o; }
        else *op = v;
      } else {
        ((float4*)(part + ((size_t)(bk*4) + m)*N))[tn*4 + cc] = v;
      }
    }
    __syncthreads();
  }
}

// lm_head GEMV (fp16), fused final RMSNorm + vp-fold of layer-2 w2 partials
__device__ void ph_lmgemv(const float* x, const float* vp, const float* ln,
                          float* sx, float* sr, int bid, int nb, int tid) {
  int ntasks = NV/128;  // 251
  if (bid >= ntasks) return;
  stage512(x, vp, ln, nullptr, sx, sr, tid);
  int c = tid & 15, ks = tid >> 4;
  float* red = sx + 4*DM;
  for (int t = bid; t < ntasks; t += nb) {
    int n8 = t*128 + c*8;
    float a[4][8];
    #pragma unroll
    for (int m = 0; m < 4; m++)
      #pragma unroll
      for (int j = 0; j < 8; j++) a[m][j] = 0.f;
    const __half* wb = g_lmh + (size_t)(ks*32)*NV + n8;
    #pragma unroll 8
    for (int kk = 0; kk < 32; kk++) {
      uint4 raw = *(const uint4*)(wb + (size_t)kk*NV);
      float2 f0 = __half22float2(*(__half2*)&raw.x);
      float2 f1 = __half22float2(*(__half2*)&raw.y);
      float2 f2 = __half22float2(*(__half2*)&raw.z);
      float2 f3 = __half22float2(*(__half2*)&raw.w);
      #pragma unroll
      for (int m = 0; m < 4; m++) {
        float xv = sx[m*DM + ks*32 + kk];
        a[m][0] = fmaf(xv, f0.x, a[m][0]); a[m][1] = fmaf(xv, f0.y, a[m][1]);
        a[m][2] = fmaf(xv, f1.x, a[m][2]); a[m][3] = fmaf(xv, f1.y, a[m][3]);
        a[m][4] = fmaf(xv, f2.x, a[m][4]); a[m][5] = fmaf(xv, f2.y, a[m][5]);
        a[m][6] = fmaf(xv, f3.x, a[m][6]); a[m][7] = fmaf(xv, f3.y, a[m][7]);
      }
    }
    #pragma unroll
    for (int m = 0; m < 4; m++) {
      #pragma unroll
      for (int j = 0; j < 8; j++) red[ks*128 + c*8 + j] = a[m][j];
      __syncthreads();
      if (tid < 128) {
        float v = red[tid];
        #pragma unroll
        for (int k2 = 1; k2 < 16; k2++) v += red[k2*128 + tid];
        g_lg[(size_t)m*NV + t*128 + tid] = v;
      }
      __syncthreads();
    }
  }
}

// softmax phase 1: per (batch, chunk) partial max/argmax/sum-exp
__device__ void ph_sm1(float* sr, int bid, int nb, int tid) {
  const int CL = NV/16;
  int* si = (int*)(sr + 256);
  for (int t = bid; t < NB*16; t += nb) {
    int b = t >> 4, ch = t & 15;
    const float* lg = g_lg + (size_t)b*NV + ch*CL;
    float mx = -3e38f; int mi = 0;
    for (int i = tid; i < CL; i += 256) {
      float v = lg[i];
      if (v > mx) { mx = v; mi = i; }
    }
    sr[tid] = mx; si[tid] = mi;
    __syncthreads();
    for (int st = 128; st; st >>= 1) {
      if (tid < st) {
        float a = sr[tid], c2 = sr[tid+st];
        int ia = si[tid], ic = si[tid+st];
        if (c2 > a || (c2 == a && ic < ia)) { sr[tid] = c2; si[tid] = ic; }
      }
      __syncthreads();
    }
    float gm = sr[0]; int gi = si[0];
    __syncthreads();
    float s = 0.f;
    for (int i = tid; i < CL; i += 256) s += expf(lg[i] - gm);
    sr[tid] = s; __syncthreads();
    for (int st = 128; st; st >>= 1) { if (tid < st) sr[tid] += sr[tid+st]; __syncthreads(); }
    if (tid == 0) { g_pm[t] = gm; g_ps[t] = sr[0]; g_pi[t] = gi + ch*CL; }
    __syncthreads();
  }
}

// merged: write probs to out AND backproj partials from logits (fp16 emb)
__device__ void ph_sm2bp(const P& p, int it, int skipbp,
                         float* sx, float* sr, int bid, int nb, int tid) {
  if (tid < 4) {
    int b = tid;
    float M = -3e38f;
    #pragma unroll
    for (int i = 0; i < 16; i++) M = fmaxf(M, g_pm[b*16+i]);
    float S = 0.f; int gi = -1;
    #pragma unroll
    for (int i = 0; i < 16; i++) {
      float m = g_pm[b*16+i];
      S += g_ps[b*16+i]*expf(m - M);
      if (gi < 0 && m == M) gi = g_pi[b*16+i];
    }
    sr[512+b] = M; sr[516+b] = 1.f/S; ((int*)sr)[520+b] = gi;
  }
  __syncthreads();
  const int CL = NV/16;
  int ntasks = 64 + BPT;
  for (int t = bid; t < ntasks; t += nb) {
    if (t < 64) {
      int b = t >> 4, ch = t & 15;
      float M = sr[512+b], inv = sr[516+b];
      const float* lg = g_lg + (size_t)b*NV + ch*CL;
      float* pd = p.out + ((size_t)b*NT + it)*NV + ch*CL;
      for (int i = tid; i < CL; i += 256) pd[i] = expf(lg[i] - M)*inv;
      if (ch == 0 && tid == 0 && p.wp)
        p.out[(size_t)NB*NT*NV + (size_t)b*NT + it] = (((int*)sr)[520+b] == 0) ? 1.f : 0.f;
    } else if (!skipbp) {
      int tt = t - 64;
      int kb = tt*BPC;
      int klen = NV - kb; if (klen > BPC) klen = BPC;
      if (klen <= 0) continue;
      for (int idx = tid; idx < 4*BPC; idx += 256) {
        int m = idx / BPC, k = idx - m*BPC;
        float v = 0.f;
        if (k < klen) v = expf(g_lg[(size_t)m*NV + kb + k] - sr[512+m]) * sr[516+m];
        sx[m*BPC + k] = v;
      }
      __syncthreads();
      int c = tid & 127, ks = tid >> 7;
      int k0 = ks*67, k1 = k0 + 67; if (k1 > klen) k1 = klen; if (k0 > klen) k0 = klen;
      float4 a[4];
      #pragma unroll
      for (int m = 0; m < 4; m++) a[m] = make_float4(0,0,0,0);
      #pragma unroll 4
      for (int k = k0; k < k1; k++) {
        uint2 raw = *(const uint2*)(g_embh + (size_t)(kb+k)*DM + c*4);
        float2 e0 = __half22float2(*(__half2*)&raw.x);
        float2 e1 = __half22float2(*(__half2*)&raw.y);
        #pragma unroll
        for (int m = 0; m < 4; m++) {
          float pm = sx[m*BPC + k];
          a[m].x = fmaf(pm, e0.x, a[m].x);
          a[m].y = fmaf(pm, e0.y, a[m].y);
          a[m].z = fmaf(pm, e1.x, a[m].z);
          a[m].w = fmaf(pm, e1.y, a[m].w);
        }
      }
      float4* xr4 = (float4*)(sx + 1024);
      if (ks == 1) {
        #pragma unroll
        for (int m = 0; m < 4; m++) xr4[c*4+m] = a[m];
      }
      __syncthreads();
      if (ks == 0) {
        #pragma unroll
        for (int m = 0; m < 4; m++) {
          float4 u = xr4[c*4+m];
          a[m].x += u.x; a[m].y += u.y; a[m].z += u.z; a[m].w += u.w;
          ((float4*)g_part)[(size_t)tt*512 + m*128 + c] = a[m];
        }
      }
      __syncthreads();
    }
  }
}

// reduce BPT backproj partials -> ye[t+1]; one warp per float4 output
__device__ void ph_redye(float* dst, int bid, int nb, int tid) {
  int gw = bid*8 + (tid >> 5), lane = tid & 31;
  if (gw >= 512) return;
  const float4* p4 = (const float4*)g_part;
  float4 v = make_float4(0,0,0,0);
  for (int t = lane; t < BPT; t += 32) {
    float4 u = p4[(size_t)t*512 + gw];
    v.x += u.x; v.y += u.y; v.z += u.z; v.w += u.w;
  }
  #pragma unroll
  for (int off = 16; off; off >>= 1) {
    v.x += __shfl_xor_sync(0xffffffffu, v.x, off);
    v.y += __shfl_xor_sync(0xffffffffu, v.y, off);
    v.z += __shfl_xor_sync(0xffffffffu, v.z, off);
    v.w += __shfl_xor_sync(0xffffffffu, v.w, off);
  }
  if (lane == 0) ((float4*)dst)[gw] = v;
}

// ---------------- the megakernel ------------------------------------------
__global__ void __launch_bounds__(256, 2) mega(P p, int nb) {
  __shared__ float sx[4*FF];     // 32 KB
  __shared__ float sr[1024];     // 4 KB
  __shared__ unsigned sg;
  int tid = threadIdx.x, bid = blockIdx.x;
  if (tid == 0) sg = 0;
  __syncthreads();

  // startup: fp16 conversions (lm + emb only) + embedding
  conv1(p.lm,  g_lmh,  (size_t)DM*NV/4, bid, nb, tid);
  conv1(p.emb, g_embh, (size_t)NV*DM/4, bid, nb, tid);
  ph_embed(p, bid, nb, tid);                                          gbar(nb,&sg);

  // ---------------- encoder (fp32) ----------------
  for (int l = 0; l < NL; l++) {
    size_t o2 = (size_t)l*DM*DM, of = (size_t)l*DM*FF;
    ph_rms(g_x, p.eln1 + (size_t)l*DM, g_h, NB*SS, sr, bid, nb, tid); gbar(nb,&sg);
    { const float* Ws[3] = { p.ewq+o2, p.ewk+o2, p.ewv+o2 };
      float* Cs[3] = { g_q, g_k, g_v };
      ph_gemm(g_h, Ws, Cs, 3, NB*SS, DM, DM, 0, 1, nullptr, sx, bid, nb, tid); }
    gbar(nb,&sg);
    ph_attn(g_q, g_k, g_v, g_att, SS, SS, (long long)SS*DM, (long long)DM,
            p.mask, NB*SS*NH, sr, bid, nb, tid);                      gbar(nb,&sg);
    { const float* Ws[1] = { p.ewo+o2 }; float* Cs[1] = { g_x };
      ph_gemm(g_att, Ws, Cs, 1, NB*SS, DM, DM, 2, 1, nullptr, sx, bid, nb, tid); }
    gbar(nb,&sg);
    ph_rms(g_x, p.eln2 + (size_t)l*DM, g_h, NB*SS, sr, bid, nb, tid); gbar(nb,&sg);
    { const float* Ws[1] = { p.ew1+of }; float* Cs[1] = { g_f };
      ph_gemm(g_h, Ws, Cs, 1, NB*SS, FF, DM, 1, 1, nullptr, sx, bid, nb, tid); }
    gbar(nb,&sg);
    { const float* Ws[1] = { p.ew2+of }; float* Cs[1] = { nullptr };
      ph_gemm(g_f, Ws, Cs, 1, NB*SS, DM, FF, 0, 4, g_gp, sx, bid, nb, tid); }
    gbar(nb,&sg);
    ph_gred(g_x, g_gp, NB*SS, DM, 4, 2, bid, nb, tid);                gbar(nb,&sg);
  }
  ph_rms(g_x, p.elnf, g_hs, NB*SS, sr, bid, nb, tid);                 gbar(nb,&sg);
  { const float* Ws[4] = { p.dck, p.dcv, p.dck + (size_t)DM*DM, p.dcv + (size_t)DM*DM };
    float* Cs[4] = { g_ck, g_cv, g_ck + (size_t)NB*SS*DM, g_cv + (size_t)NB*SS*DM };
    ph_gemm(g_hs, Ws, Cs, 4, NB*SS, DM, DM, 0, 1, nullptr, sx, bid, nb, tid); }
  gbar(nb,&sg);

  // ---------------- decoder: 16 incremental KV-cached steps ----------------
  for (int it = 0; it < NT; it++) {
    const float* xin = g_ye + (size_t)it*NB*DM;
    for (int l = 0; l < NL; l++) {
      size_t o2 = (size_t)l*DM*DM, of = (size_t)l*DM*FF;
      // ping-pong: layer 0 residual lives in g_xd, layer 1 in g_xd2 (race-free)
      const float* lx  = (l == 0) ? xin : g_xd;
      const float* lvp = (l == 0) ? nullptr : g_vp;
      float* xr = (l == 0) ? g_xd : g_xd2;
      { const float* Ws[3] = { p.dsq+o2, p.dsk+o2, p.dsv+o2 };
        float* Os[3] = { g_qd,
                         g_sk + ((size_t)l*(NT+1) + it)*NB*DM,
                         g_sv + ((size_t)l*(NT+1) + it)*NB*DM };
        ph_gemv(lx, lvp, xr, Ws, Os, 3, DM, DM, p.dln1 + (size_t)l*DM,
                0, 1, nullptr, sx, sr, bid, nb, tid); }
      gbar(nb,&sg);
      ph_attn(g_qd, g_sk + (size_t)l*(NT+1)*NB*DM, g_sv + (size_t)l*(NT+1)*NB*DM,
              g_ad, 1, it+1, (long long)DM, (long long)NB*DM, nullptr,
              NB*NH, sr, bid, nb, tid);
      gbar(nb,&sg);
      { const float* Ws[1] = { p.dso+o2 }; float* Os[1] = { xr };
        ph_gemv(g_ad, nullptr, nullptr, Ws, Os, 1, DM, DM, nullptr,
                2, 1, nullptr, sx, sr, bid, nb, tid); }
      gbar(nb,&sg);
      { const float* Ws[1] = { p.dcq+o2 }; float* Os[1] = { g_qd };
        ph_gemv(xr, nullptr, nullptr, Ws, Os, 1, DM, DM, p.dln2 + (size_t)l*DM,
                0, 1, nullptr, sx, sr, bid, nb, tid); }
      gbar(nb,&sg);
      ph_attn(g_qd, g_ck + (size_t)l*NB*SS*DM, g_cv + (size_t)l*NB*SS*DM,
              g_ad, 1, SS, (long long)SS*DM, (long long)DM, p.mask,
              NB*NH, sr, bid, nb, tid);
      gbar(nb,&sg);
      { const float* Ws[1] = { p.dco+o2 }; float* Os[1] = { xr };
        ph_gemv(g_ad, nullptr, nullptr, Ws, Os, 1, DM, DM, nullptr,
                2, 1, nullptr, sx, sr, bid, nb, tid); }
      gbar(nb,&sg);
      { const float* Ws[1] = { p.dw1+of }; float* Os[1] = { g_fd };
        ph_gemv(xr, nullptr, nullptr, Ws, Os, 1, FF, DM, p.dln3 + (size_t)l*DM,
                1, 1, nullptr, sx, sr, bid, nb, tid); }
      gbar(nb,&sg);
      { const float* Ws[1] = { p.dw2+of }; float* Os[1] = { nullptr };
        ph_gemv(g_fd, nullptr, nullptr, Ws, Os, 1, DM, FF, nullptr,
                0, 4, g_vp, sx, sr, bid, nb, tid); }
      gbar(nb,&sg);
    }
    ph_lmgemv(g_xd2, g_vp, p.dlnf, sx, sr, bid, nb, tid);
    gbar(nb,&sg);
    ph_sm1(sr, bid, nb, tid);
    gbar(nb,&sg);
    ph_sm2bp(p, it, it == NT-1, sx, sr, bid, nb, tid);
    if (it < NT-1) {
      gbar(nb,&sg);
      ph_redye(g_ye + (size_t)(it+1)*NB*DM, bid, nb, tid);
    }
    gbar(nb,&sg);
  }
  if (bid == 0 && tid == 0) {
    unsigned z = 0;
    asm volatile("st.release.gpu.u32 [%0], %1;" :: "l"(&g_cnt), "r"(z) : "memory");
  }
}

// ---------------- host ------------------------------------------------------
extern "C" void kernel_launch(void* const* d_in, const int* in_sizes, int n_in,
                              void* d_out, int out_size) {
  P p;
  p.ids   = (const int*)  d_in[0];
  p.mask  = (const float*)d_in[1];
  p.emb   = (const float*)d_in[2];
  p.ewq   = (const float*)d_in[3];
  p.ewk   = (const float*)d_in[4];
  p.ewv   = (const float*)d_in[5];
  p.ewo   = (const float*)d_in[6];
  p.eln1  = (const float*)d_in[7];
  p.ew1   = (const float*)d_in[8];
  p.ew2   = (const float*)d_in[9];
  p.eln2  = (const float*)d_in[10];
  p.elnf  = (const float*)d_in[11];
  p.dsq   = (const float*)d_in[12];
  p.dsk   = (const float*)d_in[13];
  p.dsv   = (const float*)d_in[14];
  p.dso   = (const float*)d_in[15];
  p.dln1  = (const float*)d_in[16];
  p.dcq   = (const float*)d_in[17];
  p.dck   = (const float*)d_in[18];
  p.dcv   = (const float*)d_in[19];
  p.dco   = (const float*)d_in[20];
  p.dln2  = (const float*)d_in[21];
  p.dw1   = (const float*)d_in[22];
  p.dw2   = (const float*)d_in[23];
  p.dln3  = (const float*)d_in[24];
  p.dlnf  = (const float*)d_in[25];
  p.lm    = (const float*)d_in[26];
  p.out   = (float*)d_out;
  p.wp    = (out_size > NB*NT*NV) ? 1 : 0;

  int dev = 0; cudaGetDevice(&dev);
  int sms = 0; cudaDeviceGetAttribute(&sms, cudaDevAttrMultiProcessorCount, dev);
  int nb = 2*sms;
  mega<<<nb, 256>>>(p, nb);
}